// round 1
// baseline (speedup 1.0000x reference)
#include <cuda_runtime.h>
#include <math.h>

#define BB 2
#define CC 512
#define HW 4096
#define NG 32
#define CPG 16
#define NQKV 1536

// ---- scratch (static device globals; allocation-free per harness rules) ----
__device__ float g_hn[BB * CC * HW];                       // 16 MB
__device__ float g_qkv[BB * NQKV * HW];                    // 50 MB
__device__ float g_scores[(size_t)BB * HW * HW];           // 134 MB
__device__ float g_ao[BB * CC * HW];                       // 16 MB

// ============================================================
// GroupNorm: one block per (batch, group); group = 16 ch x 4096 px
// ============================================================
__global__ void __launch_bounds__(512) gn_kernel(
    const float* __restrict__ x, const float* __restrict__ gamma,
    const float* __restrict__ beta, float* __restrict__ hn)
{
    const int bg = blockIdx.x;               // 0..63
    const int g = bg % NG;
    const size_t base = (size_t)bg * CPG * HW;
    const float* xp = x + base;
    float* op = hn + base;

    float s = 0.f, ss = 0.f;
    for (int i = threadIdx.x; i < CPG * HW; i += blockDim.x) {
        float v = xp[i];
        s += v; ss += v * v;
    }
    __shared__ float sh_s[16], sh_q[16];
    for (int o = 16; o; o >>= 1) {
        s  += __shfl_down_sync(0xffffffffu, s, o);
        ss += __shfl_down_sync(0xffffffffu, ss, o);
    }
    int warp = threadIdx.x >> 5, lane = threadIdx.x & 31;
    if (lane == 0) { sh_s[warp] = s; sh_q[warp] = ss; }
    __syncthreads();
    if (warp == 0) {
        s  = (lane < 16) ? sh_s[lane] : 0.f;
        ss = (lane < 16) ? sh_q[lane] : 0.f;
        for (int o = 16; o; o >>= 1) {
            s  += __shfl_down_sync(0xffffffffu, s, o);
            ss += __shfl_down_sync(0xffffffffu, ss, o);
        }
        if (lane == 0) { sh_s[0] = s; sh_q[0] = ss; }
    }
    __syncthreads();
    const float inv_n = 1.f / (float)(CPG * HW);
    float mean = sh_s[0] * inv_n;
    float var  = sh_q[0] * inv_n - mean * mean;
    float rstd = rsqrtf(var + 1e-6f);

    for (int i = threadIdx.x; i < CPG * HW; i += blockDim.x) {
        int ch = g * CPG + (i >> 12);
        op[i] = (xp[i] - mean) * rstd * gamma[ch] + beta[ch];
    }
}

// ============================================================
// GEMM P1: C[M,N] = W[M,K](row-major) * X[K,N] (+bias)(+resid)
// 64x64 tile, BK=16, 256 threads, 4x4 microtile
// ============================================================
__global__ void __launch_bounds__(256) gemm_wx(
    const float* __restrict__ W, const float* __restrict__ X,
    const float* __restrict__ bias, const float* __restrict__ resid,
    float* __restrict__ Cm, int M, int K, int N,
    size_t xStride, size_t cStride, size_t rStride)
{
    const int b = blockIdx.z;
    X  += (size_t)b * xStride;
    Cm += (size_t)b * cStride;
    const float* R = resid ? (resid + (size_t)b * rStride) : nullptr;
    const int m0 = blockIdx.y * 64, n0 = blockIdx.x * 64;

    __shared__ float As[16][64], Bs[16][64];
    const int t = threadIdx.x;
    const int tx = t & 15, ty = t >> 4;
    const int am = t >> 2, ak = (t & 3) << 2;
    const int bn = (t & 15) << 2, bk = t >> 4;

    const float* wp = W + (size_t)(m0 + am) * K + ak;
    const float* xp = X + (size_t)bk * N + n0 + bn;

    float acc[4][4] = {};
    for (int k0 = 0; k0 < K; k0 += 16) {
        float4 av = *(const float4*)(wp + k0);
        float4 bv = *(const float4*)(xp + (size_t)k0 * N);
        As[ak + 0][am] = av.x; As[ak + 1][am] = av.y;
        As[ak + 2][am] = av.z; As[ak + 3][am] = av.w;
        *(float4*)&Bs[bk][bn] = bv;
        __syncthreads();
#pragma unroll
        for (int k = 0; k < 16; k++) {
            float4 a  = *(const float4*)&As[k][ty << 2];
            float4 bb = *(const float4*)&Bs[k][tx << 2];
            float ar[4] = {a.x, a.y, a.z, a.w};
            float br[4] = {bb.x, bb.y, bb.z, bb.w};
#pragma unroll
            for (int i = 0; i < 4; i++)
#pragma unroll
                for (int j = 0; j < 4; j++)
                    acc[i][j] += ar[i] * br[j];
        }
        __syncthreads();
    }
#pragma unroll
    for (int i = 0; i < 4; i++) {
        int m = m0 + (ty << 2) + i;
        float bs = bias ? bias[m] : 0.f;
#pragma unroll
        for (int j = 0; j < 4; j++) {
            int n = n0 + (tx << 2) + j;
            float v = acc[i][j] + bs;
            if (R) v += R[(size_t)m * N + n];
            Cm[(size_t)m * N + n] = v;
        }
    }
}

// ============================================================
// Scores: S[n,m] = scale * sum_c Q[c,n]*K[c,m]   (both k-major)
// ============================================================
__global__ void __launch_bounds__(256) gemm_qk(float* __restrict__ S)
{
    const int b = blockIdx.z;
    const float* Q  = g_qkv + (size_t)b * NQKV * HW;
    const float* Km = Q + (size_t)CC * HW;
    float* Sb = S + (size_t)b * HW * HW;
    const int m0 = blockIdx.y * 64, n0 = blockIdx.x * 64;

    __shared__ float As[16][64], Bs[16][64];
    const int t = threadIdx.x;
    const int tx = t & 15, ty = t >> 4;
    const int lm = (t & 15) << 2, lk = t >> 4;

    const float* qp = Q  + (size_t)lk * HW + m0 + lm;
    const float* kp = Km + (size_t)lk * HW + n0 + lm;

    float acc[4][4] = {};
    for (int k0 = 0; k0 < CC; k0 += 16) {
        *(float4*)&As[lk][lm] = *(const float4*)(qp + (size_t)k0 * HW);
        *(float4*)&Bs[lk][lm] = *(const float4*)(kp + (size_t)k0 * HW);
        __syncthreads();
#pragma unroll
        for (int k = 0; k < 16; k++) {
            float4 a  = *(const float4*)&As[k][ty << 2];
            float4 bb = *(const float4*)&Bs[k][tx << 2];
            float ar[4] = {a.x, a.y, a.z, a.w};
            float br[4] = {bb.x, bb.y, bb.z, bb.w};
#pragma unroll
            for (int i = 0; i < 4; i++)
#pragma unroll
                for (int j = 0; j < 4; j++)
                    acc[i][j] += ar[i] * br[j];
        }
        __syncthreads();
    }
    const float scale = 0.04419417382415922f;  // 512^-0.5
#pragma unroll
    for (int i = 0; i < 4; i++) {
        int m = m0 + (ty << 2) + i;
#pragma unroll
        for (int j = 0; j < 4; j++) {
            int n = n0 + (tx << 2) + j;
            Sb[(size_t)m * HW + n] = acc[i][j] * scale;
        }
    }
}

// ============================================================
// Softmax over rows of S (row length 4096), in place
// ============================================================
__global__ void __launch_bounds__(256) softmax_kernel(float* __restrict__ S)
{
    float* row = S + (size_t)blockIdx.x * HW;
    const int t = threadIdx.x;
    __shared__ float sh[8];

    float m = -1e30f;
    for (int i = t; i < HW; i += 256) m = fmaxf(m, row[i]);
    for (int o = 16; o; o >>= 1) m = fmaxf(m, __shfl_xor_sync(0xffffffffu, m, o));
    if ((t & 31) == 0) sh[t >> 5] = m;
    __syncthreads();
    m = sh[0];
#pragma unroll
    for (int i = 1; i < 8; i++) m = fmaxf(m, sh[i]);

    float s = 0.f;
    for (int i = t; i < HW; i += 256) {
        float e = __expf(row[i] - m);
        row[i] = e; s += e;
    }
    for (int o = 16; o; o >>= 1) s += __shfl_xor_sync(0xffffffffu, s, o);
    __syncthreads();
    if ((t & 31) == 0) sh[t >> 5] = s;
    __syncthreads();
    s = 0.f;
#pragma unroll
    for (int i = 0; i < 8; i++) s += sh[i];
    float inv = 1.f / s;
    for (int i = t; i < HW; i += 256) row[i] *= inv;
}

// ============================================================
// AV: O[c,n] = sum_m V[c,m] * A[n,m]   (both operands k-contiguous rows)
// ============================================================
__global__ void __launch_bounds__(256) gemm_av(float* __restrict__ O)
{
    const int b = blockIdx.z;
    const float* V    = g_qkv + (size_t)b * NQKV * HW + (size_t)2 * CC * HW;
    const float* Attn = g_scores + (size_t)b * HW * HW;
    float* Ob = O + (size_t)b * CC * HW;
    const int m0 = blockIdx.y * 64, n0 = blockIdx.x * 64;

    __shared__ float As[16][64], Bs[16][64];
    const int t = threadIdx.x;
    const int tx = t & 15, ty = t >> 4;
    const int am = t >> 2, ak = (t & 3) << 2;   // for both operands (k-contig)

    const float* vp = V    + (size_t)(m0 + am) * HW + ak;
    const float* ap = Attn + (size_t)(n0 + am) * HW + ak;

    float acc[4][4] = {};
    for (int k0 = 0; k0 < HW; k0 += 16) {
        float4 av = *(const float4*)(vp + k0);
        float4 bv = *(const float4*)(ap + k0);
        As[ak + 0][am] = av.x; As[ak + 1][am] = av.y;
        As[ak + 2][am] = av.z; As[ak + 3][am] = av.w;
        Bs[ak + 0][am] = bv.x; Bs[ak + 1][am] = bv.y;
        Bs[ak + 2][am] = bv.z; Bs[ak + 3][am] = bv.w;
        __syncthreads();
#pragma unroll
        for (int k = 0; k < 16; k++) {
            float4 a  = *(const float4*)&As[k][ty << 2];
            float4 bb = *(const float4*)&Bs[k][tx << 2];
            float ar[4] = {a.x, a.y, a.z, a.w};
            float br[4] = {bb.x, bb.y, bb.z, bb.w};
#pragma unroll
            for (int i = 0; i < 4; i++)
#pragma unroll
                for (int j = 0; j < 4; j++)
                    acc[i][j] += ar[i] * br[j];
        }
        __syncthreads();
    }
#pragma unroll
    for (int i = 0; i < 4; i++) {
        int m = m0 + (ty << 2) + i;
#pragma unroll
        for (int j = 0; j < 4; j++) {
            int n = n0 + (tx << 2) + j;
            Ob[(size_t)m * HW + n] = acc[i][j];
        }
    }
}

// ============================================================
// Launch
// ============================================================
extern "C" void kernel_launch(void* const* d_in, const int* in_sizes, int n_in,
                              void* d_out, int out_size)
{
    const float* x      = (const float*)d_in[0];
    const float* gamma  = (const float*)d_in[1];
    const float* beta   = (const float*)d_in[2];
    const float* qkv_w  = (const float*)d_in[3];
    const float* qkv_b  = (const float*)d_in[4];
    const float* proj_w = (const float*)d_in[5];
    const float* proj_b = (const float*)d_in[6];
    float* out = (float*)d_out;

    float *hn, *qkv, *scores, *ao;
    cudaGetSymbolAddress((void**)&hn, g_hn);
    cudaGetSymbolAddress((void**)&qkv, g_qkv);
    cudaGetSymbolAddress((void**)&scores, g_scores);
    cudaGetSymbolAddress((void**)&ao, g_ao);

    // 1) GroupNorm
    gn_kernel<<<BB * NG, 512>>>(x, gamma, beta, hn);

    // 2) QKV = W_qkv @ hn + b     [1536,512]x[512,4096] per batch
    {
        dim3 grid(HW / 64, NQKV / 64, BB);
        gemm_wx<<<grid, 256>>>(qkv_w, hn, qkv_b, nullptr, qkv,
                               NQKV, CC, HW,
                               (size_t)CC * HW, (size_t)NQKV * HW, 0);
    }

    // 3) scores = scale * Q^T K   [4096,4096] per batch
    {
        dim3 grid(HW / 64, HW / 64, BB);
        gemm_qk<<<grid, 256>>>(scores);
    }

    // 4) softmax rows
    softmax_kernel<<<BB * HW, 256>>>(scores);

    // 5) attnout = V @ attn^T     [512,4096] per batch
    {
        dim3 grid(HW / 64, CC / 64, BB);
        gemm_av<<<grid, 256>>>(ao);
    }

    // 6) out = x + proj_w @ attnout + proj_b
    {
        dim3 grid(HW / 64, CC / 64, BB);
        gemm_wx<<<grid, 256>>>(proj_w, ao, proj_b, x, out,
                               CC, CC, HW,
                               (size_t)CC * HW, (size_t)CC * HW, (size_t)CC * HW);
    }
}

// round 3
// speedup vs baseline: 1.7018x; 1.7018x over previous
#include <cuda_runtime.h>
#include <cstdint>
#include <mma.h>
#include <math.h>
#include <type_traits>

using namespace nvcuda;

#define BB 2
#define CC 512
#define HW 4096
#define NG 32
#define CPG 16
#define NQKV 1536

// ---- scratch ----
__device__ float g_hn[BB * CC * HW];
__device__ float g_qkv[BB * NQKV * HW];
__device__ float g_scores[(size_t)BB * HW * HW];
__device__ float g_ao[BB * CC * HW];

// ============================================================
// cp.async helpers
// ============================================================
__device__ __forceinline__ void cp_async16(void* sdst, const void* gsrc) {
    unsigned s = (unsigned)__cvta_generic_to_shared(sdst);
    asm volatile("cp.async.ca.shared.global [%0], [%1], 16;\n" :: "r"(s), "l"(gsrc));
}
__device__ __forceinline__ void cp_commit() {
    asm volatile("cp.async.commit_group;\n");
}
template<int N> __device__ __forceinline__ void cp_wait() {
    asm volatile("cp.async.wait_group %0;\n" :: "n"(N));
}

// ============================================================
// GroupNorm
// ============================================================
__global__ void __launch_bounds__(512) gn_kernel(
    const float* __restrict__ x, const float* __restrict__ gamma,
    const float* __restrict__ beta, float* __restrict__ hn)
{
    const int bg = blockIdx.x;
    const int g = bg % NG;
    const size_t base = (size_t)bg * CPG * HW;
    const float* xp = x + base;
    float* op = hn + base;

    float s = 0.f, ss = 0.f;
    for (int i = threadIdx.x; i < CPG * HW; i += blockDim.x) {
        float v = xp[i];
        s += v; ss += v * v;
    }
    __shared__ float sh_s[16], sh_q[16];
    for (int o = 16; o; o >>= 1) {
        s  += __shfl_down_sync(0xffffffffu, s, o);
        ss += __shfl_down_sync(0xffffffffu, ss, o);
    }
    int warp = threadIdx.x >> 5, lane = threadIdx.x & 31;
    if (lane == 0) { sh_s[warp] = s; sh_q[warp] = ss; }
    __syncthreads();
    if (warp == 0) {
        s  = (lane < 16) ? sh_s[lane] : 0.f;
        ss = (lane < 16) ? sh_q[lane] : 0.f;
        for (int o = 16; o; o >>= 1) {
            s  += __shfl_down_sync(0xffffffffu, s, o);
            ss += __shfl_down_sync(0xffffffffu, ss, o);
        }
        if (lane == 0) { sh_s[0] = s; sh_q[0] = ss; }
    }
    __syncthreads();
    const float inv_n = 1.f / (float)(CPG * HW);
    float mean = sh_s[0] * inv_n;
    float var  = sh_q[0] * inv_n - mean * mean;
    float rstd = rsqrtf(var + 1e-6f);

    for (int i = threadIdx.x; i < CPG * HW; i += blockDim.x) {
        int ch = g * CPG + (i >> 12);
        op[i] = (xp[i] - mean) * rstd * gamma[ch] + beta[ch];
    }
}

// ============================================================
// TF32 tensor-core GEMM: C[M,N] = alpha * op(A) * op(B) (+bias)(+resid)
//  AROW: A[m*lda+k] else A[k*lda+m]
//  BROW: B[k*ldb+n] else B[n*ldb+k]
//  128x128 block tile, BK=16, 256 threads, warp tile 32x64, cp.async 2-stage
// ============================================================
template<bool AROW, bool BROW>
__global__ void __launch_bounds__(256) gemm_tc(
    const float* __restrict__ A, const float* __restrict__ B,
    const float* __restrict__ bias, const float* __restrict__ Rsd,
    float* __restrict__ C,
    int K, int N, int lda, int ldb,
    size_t aStride, size_t bStride, size_t cStride, size_t rStride,
    float alpha)
{
    extern __shared__ float smem[];
    const int bz = blockIdx.z;
    A += aStride * bz; B += bStride * bz; C += cStride * bz;
    const float* R = Rsd ? (Rsd + rStride * bz) : nullptr;
    const int m0 = blockIdx.y * 128, n0 = blockIdx.x * 128;

    constexpr int LDA = AROW ? 24 : 136;          // padded smem strides
    constexpr int LDB = BROW ? 136 : 24;
    constexpr int ASTG = AROW ? 128 * 24 : 16 * 136;
    constexpr int BSTG = BROW ? 16 * 136 : 128 * 24;
    constexpr int STG = ASTG + BSTG;

    const int t = threadIdx.x;
    const int wid = t >> 5;
    const int wm = wid & 3;          // 4 warps along M (32 rows each)
    const int wn = wid >> 2;         // 2 warps along N (64 cols each)

    using ALay = typename std::conditional<AROW, wmma::row_major, wmma::col_major>::type;
    using BLay = typename std::conditional<BROW, wmma::row_major, wmma::col_major>::type;
    wmma::fragment<wmma::matrix_a, 16, 16, 8, wmma::precision::tf32, ALay> af[2];
    wmma::fragment<wmma::matrix_b, 16, 16, 8, wmma::precision::tf32, BLay> bf[4];
    wmma::fragment<wmma::accumulator, 16, 16, 8, float> acc[2][4];
#pragma unroll
    for (int i = 0; i < 2; i++)
#pragma unroll
        for (int j = 0; j < 4; j++)
            wmma::fill_fragment(acc[i][j], 0.f);

    // ---- async tile loader ----
    auto load_stage = [&](int st, int k0) {
        float* As = smem + st * STG;
        float* Bs = As + ASTG;
#pragma unroll
        for (int c = t; c < 512; c += 256) {
            if (AROW) {
                int m = c >> 2, kk = (c & 3) << 2;
                cp_async16(As + m * LDA + kk,
                           A + (size_t)(m0 + m) * lda + k0 + kk);
            } else {
                int k = c >> 5, mm = (c & 31) << 2;
                cp_async16(As + k * LDA + mm,
                           A + (size_t)(k0 + k) * lda + m0 + mm);
            }
        }
#pragma unroll
        for (int c = t; c < 512; c += 256) {
            if (BROW) {
                int k = c >> 5, nn = (c & 31) << 2;
                cp_async16(Bs + k * LDB + nn,
                           B + (size_t)(k0 + k) * ldb + n0 + nn);
            } else {
                int n = c >> 2, kk = (c & 3) << 2;
                cp_async16(Bs + n * LDB + kk,
                           B + (size_t)(n0 + n) * ldb + k0 + kk);
            }
        }
    };

    const int KT = K >> 4;
    load_stage(0, 0);
    cp_commit();

    for (int kt = 0; kt < KT; kt++) {
        if (kt + 1 < KT) load_stage((kt + 1) & 1, (kt + 1) << 4);
        cp_commit();                       // possibly-empty group keeps accounting uniform
        cp_wait<1>();
        __syncthreads();

        const float* As = smem + (kt & 1) * STG;
        const float* Bs = As + ASTG;
#pragma unroll
        for (int ks = 0; ks < 16; ks += 8) {
#pragma unroll
            for (int i = 0; i < 2; i++) {
                const float* ap = AROW
                    ? As + (wm * 32 + i * 16) * LDA + ks
                    : As + ks * LDA + (wm * 32 + i * 16);
                wmma::load_matrix_sync(af[i], ap, LDA);
#pragma unroll
                for (int e = 0; e < af[i].num_elements; e++)
                    af[i].x[e] = wmma::__float_to_tf32(af[i].x[e]);
            }
#pragma unroll
            for (int j = 0; j < 4; j++) {
                const float* bp = BROW
                    ? Bs + ks * LDB + (wn * 64 + j * 16)
                    : Bs + (wn * 64 + j * 16) * LDB + ks;
                wmma::load_matrix_sync(bf[j], bp, LDB);
#pragma unroll
                for (int e = 0; e < bf[j].num_elements; e++)
                    bf[j].x[e] = wmma::__float_to_tf32(bf[j].x[e]);
            }
#pragma unroll
            for (int i = 0; i < 2; i++)
#pragma unroll
                for (int j = 0; j < 4; j++)
                    wmma::mma_sync(acc[i][j], af[i], bf[j], acc[i][j]);
        }
        __syncthreads();
    }

    // ---- epilogue through smem staging (128 x 132) ----
    float* Csh = smem;
#pragma unroll
    for (int i = 0; i < 2; i++)
#pragma unroll
        for (int j = 0; j < 4; j++)
            wmma::store_matrix_sync(Csh + (wm * 32 + i * 16) * 132 + wn * 64 + j * 16,
                                    acc[i][j], 132, wmma::mem_row_major);
    __syncthreads();

    const int c4 = (t & 31) << 2;
    for (int r = t >> 5; r < 128; r += 8) {
        float4 v = *(const float4*)(Csh + r * 132 + c4);
        const int m = m0 + r;
        float bsv = bias ? bias[m] : 0.f;
        v.x = v.x * alpha + bsv;
        v.y = v.y * alpha + bsv;
        v.z = v.z * alpha + bsv;
        v.w = v.w * alpha + bsv;
        if (R) {
            float4 rv = *(const float4*)(R + (size_t)m * N + n0 + c4);
            v.x += rv.x; v.y += rv.y; v.z += rv.z; v.w += rv.w;
        }
        *(float4*)(C + (size_t)m * N + n0 + c4) = v;
    }
}

// ============================================================
// Softmax (rows of 4096, in place)
// ============================================================
__global__ void __launch_bounds__(256) softmax_kernel(float* __restrict__ S)
{
    float* row = S + (size_t)blockIdx.x * HW;
    const int t = threadIdx.x;
    __shared__ float sh[8];

    float m = -1e30f;
    for (int i = t; i < HW; i += 256) m = fmaxf(m, row[i]);
    for (int o = 16; o; o >>= 1) m = fmaxf(m, __shfl_xor_sync(0xffffffffu, m, o));
    if ((t & 31) == 0) sh[t >> 5] = m;
    __syncthreads();
    m = sh[0];
#pragma unroll
    for (int i = 1; i < 8; i++) m = fmaxf(m, sh[i]);

    float s = 0.f;
    for (int i = t; i < HW; i += 256) {
        float e = __expf(row[i] - m);
        row[i] = e; s += e;
    }
    for (int o = 16; o; o >>= 1) s += __shfl_xor_sync(0xffffffffu, s, o);
    __syncthreads();
    if ((t & 31) == 0) sh[t >> 5] = s;
    __syncthreads();
    s = 0.f;
#pragma unroll
    for (int i = 0; i < 8; i++) s += sh[i];
    float inv = 1.f / s;
    for (int i = t; i < HW; i += 256) row[i] *= inv;
}

// ============================================================
// Launch
// ============================================================
static const int SMEM_BYTES = 128 * 132 * 4;   // 67584; >= 2-stage pipeline too

extern "C" void kernel_launch(void* const* d_in, const int* in_sizes, int n_in,
                              void* d_out, int out_size)
{
    const float* x      = (const float*)d_in[0];
    const float* gamma  = (const float*)d_in[1];
    const float* beta   = (const float*)d_in[2];
    const float* qkv_w  = (const float*)d_in[3];
    const float* qkv_b  = (const float*)d_in[4];
    const float* proj_w = (const float*)d_in[5];
    const float* proj_b = (const float*)d_in[6];
    float* out = (float*)d_out;

    float *hn, *qkv, *scores, *ao;
    cudaGetSymbolAddress((void**)&hn, g_hn);
    cudaGetSymbolAddress((void**)&qkv, g_qkv);
    cudaGetSymbolAddress((void**)&scores, g_scores);
    cudaGetSymbolAddress((void**)&ao, g_ao);

    cudaFuncSetAttribute(gemm_tc<true,  true >, cudaFuncAttributeMaxDynamicSharedMemorySize, SMEM_BYTES);
    cudaFuncSetAttribute(gemm_tc<false, true >, cudaFuncAttributeMaxDynamicSharedMemorySize, SMEM_BYTES);
    cudaFuncSetAttribute(gemm_tc<true,  false>, cudaFuncAttributeMaxDynamicSharedMemorySize, SMEM_BYTES);

    // 1) GroupNorm
    gn_kernel<<<BB * NG, 512>>>(x, gamma, beta, hn);

    // 2) QKV = W_qkv @ hn + b
    {
        dim3 grid(HW / 128, NQKV / 128, BB);
        gemm_tc<true, true><<<grid, 256, SMEM_BYTES>>>(
            qkv_w, hn, qkv_b, nullptr, qkv,
            CC, HW, CC, HW,
            0, (size_t)CC * HW, (size_t)NQKV * HW, 0, 1.f);
    }

    // 3) scores = scale * Q^T K   (A col-major view of Q, B row-major K)
    {
        dim3 grid(HW / 128, HW / 128, BB);
        gemm_tc<false, true><<<grid, 256, SMEM_BYTES>>>(
            qkv, qkv + (size_t)CC * HW, nullptr, nullptr, scores,
            CC, HW, HW, HW,
            (size_t)NQKV * HW, (size_t)NQKV * HW, (size_t)HW * HW, 0,
            0.04419417382415922f);
    }

    // 4) softmax rows
    softmax_kernel<<<BB * HW, 256>>>(scores);

    // 5) attnout = V @ attn^T  (A row-major V, B col-major view of attn)
    {
        dim3 grid(HW / 128, CC / 128, BB);
        gemm_tc<true, false><<<grid, 256, SMEM_BYTES>>>(
            qkv + (size_t)2 * CC * HW, scores, nullptr, nullptr, ao,
            HW, HW, HW, HW,
            (size_t)NQKV * HW, (size_t)HW * HW, (size_t)CC * HW, 0, 1.f);
    }

    // 6) out = x + proj_w @ attnout + proj_b
    {
        dim3 grid(HW / 128, CC / 128, BB);
        gemm_tc<true, true><<<grid, 256, SMEM_BYTES>>>(
            proj_w, ao, proj_b, x, out,
            CC, HW, CC, HW,
            0, (size_t)CC * HW, (size_t)CC * HW, (size_t)CC * HW, 1.f);
    }
}

// round 6
// speedup vs baseline: 3.2078x; 1.8849x over previous
#include <cuda_runtime.h>
#include <cstdint>
#include <cuda_bf16.h>
#include <mma.h>
#include <math.h>
#include <type_traits>

using namespace nvcuda;

#define BB 2
#define CC 512
#define HW 4096
#define NG 32
#define CPG 16
#define NQKV 1536

// ---- scratch ----
__device__ __align__(256) float g_hn[BB * CC * HW];                     // 16 MB
__device__ __align__(256) __nv_bfloat16 g_qkv[BB * NQKV * HW];          // 25 MB
__device__ __align__(256) float g_scores[(size_t)BB * HW * HW];         // 134 MB
__device__ __align__(256) __nv_bfloat16 g_attn[(size_t)BB * HW * HW];   // 67 MB
__device__ __align__(256) float g_ao[BB * CC * HW];                     // 16 MB

// ============================================================
// cp.async helpers
// ============================================================
__device__ __forceinline__ void cp_async16(void* sdst, const void* gsrc) {
    unsigned s = (unsigned)__cvta_generic_to_shared(sdst);
    asm volatile("cp.async.ca.shared.global [%0], [%1], 16;\n" :: "r"(s), "l"(gsrc));
}
__device__ __forceinline__ void cp_commit() {
    asm volatile("cp.async.commit_group;\n");
}
template<int N> __device__ __forceinline__ void cp_wait() {
    asm volatile("cp.async.wait_group %0;\n" :: "n"(N));
}

// ---- bf16 GEMM smem layout (shared between host sizing and kernel) ----
template<bool AROW, bool BROW>
struct BF16Lay {
    static const int LDA  = AROW ? 48 : 144;   // elems; *2B multiples of 32B
    static const int LDB  = BROW ? 144 : 48;
    static const int ASTG = AROW ? 128 * 48 : 32 * 144;
    static const int BSTG = BROW ? 32 * 144 : 128 * 48;
    static const int STG  = ASTG + BSTG;
    static const int BYTES = 2 * STG * 2;      // 2 stages, bf16
};

// ============================================================
// GroupNorm
// ============================================================
__global__ void __launch_bounds__(512) gn_kernel(
    const float* __restrict__ x, const float* __restrict__ gamma,
    const float* __restrict__ beta, float* __restrict__ hn)
{
    const int bg = blockIdx.x;
    const int g = bg % NG;
    const size_t base = (size_t)bg * CPG * HW;
    const float* xp = x + base;
    float* op = hn + base;

    float s = 0.f, ss = 0.f;
    for (int i = threadIdx.x; i < CPG * HW; i += blockDim.x) {
        float v = xp[i];
        s += v; ss += v * v;
    }
    __shared__ float sh_s[16], sh_q[16];
    for (int o = 16; o; o >>= 1) {
        s  += __shfl_down_sync(0xffffffffu, s, o);
        ss += __shfl_down_sync(0xffffffffu, ss, o);
    }
    int warp = threadIdx.x >> 5, lane = threadIdx.x & 31;
    if (lane == 0) { sh_s[warp] = s; sh_q[warp] = ss; }
    __syncthreads();
    if (warp == 0) {
        s  = (lane < 16) ? sh_s[lane] : 0.f;
        ss = (lane < 16) ? sh_q[lane] : 0.f;
        for (int o = 16; o; o >>= 1) {
            s  += __shfl_down_sync(0xffffffffu, s, o);
            ss += __shfl_down_sync(0xffffffffu, ss, o);
        }
        if (lane == 0) { sh_s[0] = s; sh_q[0] = ss; }
    }
    __syncthreads();
    const float inv_n = 1.f / (float)(CPG * HW);
    float mean = sh_s[0] * inv_n;
    float var  = sh_q[0] * inv_n - mean * mean;
    float rstd = rsqrtf(var + 1e-6f);

    for (int i = threadIdx.x; i < CPG * HW; i += blockDim.x) {
        int ch = g * CPG + (i >> 12);
        op[i] = (xp[i] - mean) * rstd * gamma[ch] + beta[ch];
    }
}

// ============================================================
// TF32 tensor-core GEMM (weight GEMMs): C = A(row) * B(row) (+bias)(+resid)
// ============================================================
template<typename OUT>
__global__ void __launch_bounds__(256) gemm_tf32(
    const float* __restrict__ A, const float* __restrict__ B,
    const float* __restrict__ bias, const float* __restrict__ Rsd,
    OUT* __restrict__ C,
    int K, int N, int lda, int ldb,
    size_t bStride, size_t cStride, size_t rStride)
{
    extern __shared__ float smem[];
    const int bz = blockIdx.z;
    B += bStride * bz; C += cStride * bz;
    const float* R = Rsd ? (Rsd + rStride * bz) : nullptr;
    const int m0 = blockIdx.y * 128, n0 = blockIdx.x * 128;

    constexpr int LDA = 24;
    constexpr int LDB = 136;
    constexpr int ASTG = 128 * 24;
    constexpr int BSTG = 16 * 136;
    constexpr int STG = ASTG + BSTG;

    const int t = threadIdx.x;
    const int wid = t >> 5;
    const int wm = wid & 3;
    const int wn = wid >> 2;

    wmma::fragment<wmma::matrix_a, 16, 16, 8, wmma::precision::tf32, wmma::row_major> af[2];
    wmma::fragment<wmma::matrix_b, 16, 16, 8, wmma::precision::tf32, wmma::row_major> bf[4];
    wmma::fragment<wmma::accumulator, 16, 16, 8, float> acc[2][4];
#pragma unroll
    for (int i = 0; i < 2; i++)
#pragma unroll
        for (int j = 0; j < 4; j++)
            wmma::fill_fragment(acc[i][j], 0.f);

    auto load_stage = [&](int st, int k0) {
        float* As = smem + st * STG;
        float* Bs = As + ASTG;
#pragma unroll
        for (int c = t; c < 512; c += 256) {
            int m = c >> 2, kk = (c & 3) << 2;
            cp_async16(As + m * LDA + kk, A + (size_t)(m0 + m) * lda + k0 + kk);
        }
#pragma unroll
        for (int c = t; c < 512; c += 256) {
            int k = c >> 5, nn = (c & 31) << 2;
            cp_async16(Bs + k * LDB + nn, B + (size_t)(k0 + k) * ldb + n0 + nn);
        }
    };

    const int KT = K >> 4;
    load_stage(0, 0);
    cp_commit();

    for (int kt = 0; kt < KT; kt++) {
        if (kt + 1 < KT) load_stage((kt + 1) & 1, (kt + 1) << 4);
        cp_commit();
        cp_wait<1>();
        __syncthreads();

        const float* As = smem + (kt & 1) * STG;
        const float* Bs = As + ASTG;
#pragma unroll
        for (int ks = 0; ks < 16; ks += 8) {
#pragma unroll
            for (int i = 0; i < 2; i++)
                wmma::load_matrix_sync(af[i], As + (wm * 32 + i * 16) * LDA + ks, LDA);
#pragma unroll
            for (int j = 0; j < 4; j++)
                wmma::load_matrix_sync(bf[j], Bs + ks * LDB + (wn * 64 + j * 16), LDB);
#pragma unroll
            for (int i = 0; i < 2; i++)
#pragma unroll
                for (int j = 0; j < 4; j++)
                    wmma::mma_sync(acc[i][j], af[i], bf[j], acc[i][j]);
        }
        __syncthreads();
    }

    // epilogue through smem staging (128 x 132)
    float* Csh = smem;
#pragma unroll
    for (int i = 0; i < 2; i++)
#pragma unroll
        for (int j = 0; j < 4; j++)
            wmma::store_matrix_sync(Csh + (wm * 32 + i * 16) * 132 + wn * 64 + j * 16,
                                    acc[i][j], 132, wmma::mem_row_major);
    __syncthreads();

    const int c4 = (t & 31) << 2;
    for (int r = t >> 5; r < 128; r += 8) {
        float4 v = *(const float4*)(Csh + r * 132 + c4);
        const int m = m0 + r;
        float bsv = bias ? bias[m] : 0.f;
        v.x += bsv; v.y += bsv; v.z += bsv; v.w += bsv;
        if (R) {
            float4 rv = *(const float4*)(R + (size_t)m * N + n0 + c4);
            v.x += rv.x; v.y += rv.y; v.z += rv.z; v.w += rv.w;
        }
        OUT* cp = C + (size_t)m * N + n0 + c4;
        if (std::is_same<OUT, float>::value) {
            *(float4*)(void*)cp = v;
        } else {
            __nv_bfloat16* bp = (__nv_bfloat16*)cp;
            bp[0] = __float2bfloat16(v.x);
            bp[1] = __float2bfloat16(v.y);
            bp[2] = __float2bfloat16(v.z);
            bp[3] = __float2bfloat16(v.w);
        }
    }
}

// ============================================================
// BF16 tensor-core GEMM (attention GEMMs): C = alpha * op(A)*op(B)
// ============================================================
template<bool AROW, bool BROW>
__global__ void __launch_bounds__(256) gemm_bf16(
    const __nv_bfloat16* __restrict__ A, const __nv_bfloat16* __restrict__ B,
    float* __restrict__ C,
    int K, int ldc, int lda, int ldb,
    size_t aStride, size_t bStride, size_t cStride,
    float alpha)
{
    extern __shared__ __nv_bfloat16 smemh[];
    using L = BF16Lay<AROW, BROW>;
    const int bz = blockIdx.z;
    A += aStride * bz; B += bStride * bz; C += cStride * bz;
    const int m0 = blockIdx.y * 128, n0 = blockIdx.x * 128;

    const int t = threadIdx.x;
    const int wid = t >> 5;
    const int wm = wid & 3;
    const int wn = wid >> 2;

    using ALay = typename std::conditional<AROW, wmma::row_major, wmma::col_major>::type;
    using BLay = typename std::conditional<BROW, wmma::row_major, wmma::col_major>::type;
    wmma::fragment<wmma::matrix_a, 16, 16, 16, __nv_bfloat16, ALay> af[2];
    wmma::fragment<wmma::matrix_b, 16, 16, 16, __nv_bfloat16, BLay> bf[4];
    wmma::fragment<wmma::accumulator, 16, 16, 16, float> acc[2][4];
#pragma unroll
    for (int i = 0; i < 2; i++)
#pragma unroll
        for (int j = 0; j < 4; j++)
            wmma::fill_fragment(acc[i][j], 0.f);

    auto load_stage = [&](int st, int k0) {
        __nv_bfloat16* As = smemh + st * L::STG;
        __nv_bfloat16* Bs = As + L::ASTG;
#pragma unroll
        for (int c = t; c < 512; c += 256) {
            if (AROW) {           // 128 rows x 32 k
                int m = c >> 2, kk = (c & 3) << 3;
                cp_async16(As + m * L::LDA + kk, A + (size_t)(m0 + m) * lda + k0 + kk);
            } else {              // 32 k-rows x 128 m
                int k = c >> 4, mm = (c & 15) << 3;
                cp_async16(As + k * L::LDA + mm, A + (size_t)(k0 + k) * lda + m0 + mm);
            }
        }
#pragma unroll
        for (int c = t; c < 512; c += 256) {
            if (BROW) {           // 32 k-rows x 128 n
                int k = c >> 4, nn = (c & 15) << 3;
                cp_async16(Bs + k * L::LDB + nn, B + (size_t)(k0 + k) * ldb + n0 + nn);
            } else {              // 128 n-rows x 32 k
                int n = c >> 2, kk = (c & 3) << 3;
                cp_async16(Bs + n * L::LDB + kk, B + (size_t)(n0 + n) * ldb + k0 + kk);
            }
        }
    };

    const int KT = K >> 5;
    load_stage(0, 0);
    cp_commit();

    for (int kt = 0; kt < KT; kt++) {
        if (kt + 1 < KT) load_stage((kt + 1) & 1, (kt + 1) << 5);
        cp_commit();
        cp_wait<1>();
        __syncthreads();

        const __nv_bfloat16* As = smemh + (kt & 1) * L::STG;
        const __nv_bfloat16* Bs = As + L::ASTG;
#pragma unroll
        for (int ks = 0; ks < 32; ks += 16) {
#pragma unroll
            for (int i = 0; i < 2; i++) {
                const __nv_bfloat16* ap = AROW
                    ? As + (wm * 32 + i * 16) * L::LDA + ks
                    : As + ks * L::LDA + (wm * 32 + i * 16);
                wmma::load_matrix_sync(af[i], ap, L::LDA);
            }
#pragma unroll
            for (int j = 0; j < 4; j++) {
                const __nv_bfloat16* bp = BROW
                    ? Bs + ks * L::LDB + (wn * 64 + j * 16)
                    : Bs + (wn * 64 + j * 16) * L::LDB + ks;
                wmma::load_matrix_sync(bf[j], bp, L::LDB);
            }
#pragma unroll
            for (int i = 0; i < 2; i++)
#pragma unroll
                for (int j = 0; j < 4; j++)
                    wmma::mma_sync(acc[i][j], af[i], bf[j], acc[i][j]);
        }
        __syncthreads();
    }

    // direct global store with alpha
#pragma unroll
    for (int i = 0; i < 2; i++)
#pragma unroll
        for (int j = 0; j < 4; j++) {
#pragma unroll
            for (int e = 0; e < acc[i][j].num_elements; e++)
                acc[i][j].x[e] *= alpha;
            wmma::store_matrix_sync(
                C + (size_t)(m0 + wm * 32 + i * 16) * ldc + n0 + wn * 64 + j * 16,
                acc[i][j], ldc, wmma::mem_row_major);
        }
}

// ============================================================
// Softmax (fp32 rows of 4096 -> bf16 attn)
// ============================================================
__global__ void __launch_bounds__(256) softmax_kernel(
    const float* __restrict__ S, __nv_bfloat16* __restrict__ Aout)
{
    const float* row = S + (size_t)blockIdx.x * HW;
    __nv_bfloat16* arow = Aout + (size_t)blockIdx.x * HW;
    const int t = threadIdx.x;
    __shared__ float sh[8];

    float m = -1e30f;
    for (int i = t; i < HW; i += 256) m = fmaxf(m, row[i]);
    for (int o = 16; o; o >>= 1) m = fmaxf(m, __shfl_xor_sync(0xffffffffu, m, o));
    if ((t & 31) == 0) sh[t >> 5] = m;
    __syncthreads();
    m = sh[0];
#pragma unroll
    for (int i = 1; i < 8; i++) m = fmaxf(m, sh[i]);

    float s = 0.f;
    float ebuf[16];
    for (int i = t, c = 0; i < HW; i += 256, c++) {
        float e = __expf(row[i] - m);
        ebuf[c] = e; s += e;
    }
    for (int o = 16; o; o >>= 1) s += __shfl_xor_sync(0xffffffffu, s, o);
    __syncthreads();
    if ((t & 31) == 0) sh[t >> 5] = s;
    __syncthreads();
    s = 0.f;
#pragma unroll
    for (int i = 0; i < 8; i++) s += sh[i];
    float inv = 1.f / s;
    for (int i = t, c = 0; i < HW; i += 256, c++)
        arow[i] = __float2bfloat16(ebuf[c] * inv);
}

// ============================================================
// Launch
// ============================================================
static const int SMEM_TF32 = 128 * 132 * 4;                   // 67584 B
static const int SMEM_QK   = BF16Lay<false, true >::BYTES;    // 36864 B
static const int SMEM_AV   = BF16Lay<true,  false>::BYTES;    // 49152 B

extern "C" void kernel_launch(void* const* d_in, const int* in_sizes, int n_in,
                              void* d_out, int out_size)
{
    const float* x      = (const float*)d_in[0];
    const float* gamma  = (const float*)d_in[1];
    const float* beta   = (const float*)d_in[2];
    const float* qkv_w  = (const float*)d_in[3];
    const float* qkv_b  = (const float*)d_in[4];
    const float* proj_w = (const float*)d_in[5];
    const float* proj_b = (const float*)d_in[6];
    float* out = (float*)d_out;

    float *hn, *scores, *ao;
    __nv_bfloat16 *qkv, *attn;
    cudaGetSymbolAddress((void**)&hn, g_hn);
    cudaGetSymbolAddress((void**)&qkv, g_qkv);
    cudaGetSymbolAddress((void**)&scores, g_scores);
    cudaGetSymbolAddress((void**)&attn, g_attn);
    cudaGetSymbolAddress((void**)&ao, g_ao);

    cudaFuncSetAttribute(gemm_tf32<__nv_bfloat16>, cudaFuncAttributeMaxDynamicSharedMemorySize, SMEM_TF32);
    cudaFuncSetAttribute(gemm_tf32<float>,         cudaFuncAttributeMaxDynamicSharedMemorySize, SMEM_TF32);
    cudaFuncSetAttribute(gemm_bf16<false, true >,  cudaFuncAttributeMaxDynamicSharedMemorySize, SMEM_QK);
    cudaFuncSetAttribute(gemm_bf16<true,  false>,  cudaFuncAttributeMaxDynamicSharedMemorySize, SMEM_AV);

    // 1) GroupNorm
    gn_kernel<<<BB * NG, 512>>>(x, gamma, beta, hn);

    // 2) QKV = W_qkv @ hn + b  -> bf16
    {
        dim3 grid(HW / 128, NQKV / 128, BB);
        gemm_tf32<__nv_bfloat16><<<grid, 256, SMEM_TF32>>>(
            qkv_w, hn, qkv_b, nullptr, qkv,
            CC, HW, CC, HW,
            (size_t)CC * HW, (size_t)NQKV * HW, 0);
    }

    // 3) scores = scale * Q^T K  (A = Q col-major, B = K row-major), fp32 out
    {
        dim3 grid(HW / 128, HW / 128, BB);
        gemm_bf16<false, true><<<grid, 256, SMEM_QK>>>(
            qkv, qkv + (size_t)CC * HW, scores,
            CC, HW, HW, HW,
            (size_t)NQKV * HW, (size_t)NQKV * HW, (size_t)HW * HW,
            0.04419417382415922f);
    }

    // 4) softmax rows -> bf16 attn
    softmax_kernel<<<BB * HW, 256>>>(scores, attn);

    // 5) attnout = V @ attn^T  (A = V row-major, B = attn col-major), fp32 out
    {
        dim3 grid(HW / 128, CC / 128, BB);
        gemm_bf16<true, false><<<grid, 256, SMEM_AV>>>(
            qkv + (size_t)2 * CC * HW, attn, ao,
            HW, HW, HW, HW,
            (size_t)NQKV * HW, (size_t)HW * HW, (size_t)CC * HW,
            1.f);
    }

    // 6) out = x + proj_w @ attnout + proj_b
    {
        dim3 grid(HW / 128, CC / 128, BB);
        gemm_tf32<float><<<grid, 256, SMEM_TF32>>>(
            proj_w, ao, proj_b, x, out,
            CC, HW, CC, HW,
            (size_t)CC * HW, (size_t)CC * HW, (size_t)CC * HW);
    }
}

// round 7
// speedup vs baseline: 4.3760x; 1.3642x over previous
#include <cuda_runtime.h>
#include <cstdint>
#include <cuda_bf16.h>
#include <mma.h>
#include <math.h>
#include <type_traits>

using namespace nvcuda;

#define BB 2
#define CC 512
#define HW 4096
#define NG 32
#define CPG 16
#define NQKV 1536

// ---- scratch ----
__device__ __align__(256) __nv_bfloat16 g_hn[BB * CC * HW];             // 8 MB
__device__ __align__(256) __nv_bfloat16 g_qkv[BB * NQKV * HW];          // 25 MB
__device__ __align__(256) __nv_bfloat16 g_scores[(size_t)BB * HW * HW]; // 67 MB
__device__ __align__(256) __nv_bfloat16 g_attn[(size_t)BB * HW * HW];   // 67 MB
__device__ __align__(256) __nv_bfloat16 g_ao[BB * CC * HW];             // 8 MB
__device__ __align__(256) __nv_bfloat16 g_qw_h[NQKV * CC];
__device__ __align__(256) __nv_bfloat16 g_pw_h[CC * CC];

// ============================================================
// cp.async helpers
// ============================================================
__device__ __forceinline__ void cp_async16(void* sdst, const void* gsrc) {
    unsigned s = (unsigned)__cvta_generic_to_shared(sdst);
    asm volatile("cp.async.ca.shared.global [%0], [%1], 16;\n" :: "r"(s), "l"(gsrc));
}
__device__ __forceinline__ void cp_commit() {
    asm volatile("cp.async.commit_group;\n");
}
template<int N> __device__ __forceinline__ void cp_wait() {
    asm volatile("cp.async.wait_group %0;\n" :: "n"(N));
}

// ---- bf16 GEMM smem pipeline layout ----
template<bool AROW, bool BROW>
struct BF16Lay {
    static const int LDA  = AROW ? 48 : 144;
    static const int LDB  = BROW ? 144 : 48;
    static const int ASTG = AROW ? 128 * 48 : 32 * 144;
    static const int BSTG = BROW ? 32 * 144 : 128 * 48;
    static const int STG  = ASTG + BSTG;
};
static const int SMEM_GEMM = 128 * 132 * 4;   // epilogue staging dominates: 67584 B

// ============================================================
// fp32 -> bf16 conversion (weights)
// ============================================================
__global__ void cvt_kernel(const float* __restrict__ s, __nv_bfloat16* __restrict__ d, int n)
{
    for (int i = blockIdx.x * blockDim.x + threadIdx.x; i < n; i += gridDim.x * blockDim.x)
        d[i] = __float2bfloat16(s[i]);
}

// ============================================================
// GroupNorm -> bf16
// ============================================================
__global__ void __launch_bounds__(512) gn_kernel(
    const float* __restrict__ x, const float* __restrict__ gamma,
    const float* __restrict__ beta, __nv_bfloat16* __restrict__ hn)
{
    const int bg = blockIdx.x;
    const int g = bg % NG;
    const size_t base = (size_t)bg * CPG * HW;
    const float* xp = x + base;
    __nv_bfloat16* op = hn + base;

    float s = 0.f, ss = 0.f;
    for (int i = threadIdx.x; i < CPG * HW; i += blockDim.x) {
        float v = xp[i];
        s += v; ss += v * v;
    }
    __shared__ float sh_s[16], sh_q[16];
    for (int o = 16; o; o >>= 1) {
        s  += __shfl_down_sync(0xffffffffu, s, o);
        ss += __shfl_down_sync(0xffffffffu, ss, o);
    }
    int warp = threadIdx.x >> 5, lane = threadIdx.x & 31;
    if (lane == 0) { sh_s[warp] = s; sh_q[warp] = ss; }
    __syncthreads();
    if (warp == 0) {
        s  = (lane < 16) ? sh_s[lane] : 0.f;
        ss = (lane < 16) ? sh_q[lane] : 0.f;
        for (int o = 16; o; o >>= 1) {
            s  += __shfl_down_sync(0xffffffffu, s, o);
            ss += __shfl_down_sync(0xffffffffu, ss, o);
        }
        if (lane == 0) { sh_s[0] = s; sh_q[0] = ss; }
    }
    __syncthreads();
    const float inv_n = 1.f / (float)(CPG * HW);
    float mean = sh_s[0] * inv_n;
    float var  = sh_q[0] * inv_n - mean * mean;
    float rstd = rsqrtf(var + 1e-6f);

    for (int i = threadIdx.x; i < CPG * HW; i += blockDim.x) {
        int ch = g * CPG + (i >> 12);
        op[i] = __float2bfloat16((xp[i] - mean) * rstd * gamma[ch] + beta[ch]);
    }
}

// ============================================================
// BF16 tensor-core GEMM: C = alpha*op(A)*op(B) (+bias)(+resid fp32)
//  AROW: A[m*lda+k] else A[k*lda+m];  BROW: B[k*ldb+n] else B[n*ldb+k]
//  128x128 tile, BK=32, 256 thr, warp 32x64, smem-staged epilogue
// ============================================================
template<bool AROW, bool BROW, typename OUT>
__global__ void __launch_bounds__(256) gemm_bf16v2(
    const __nv_bfloat16* __restrict__ A, const __nv_bfloat16* __restrict__ B,
    const float* __restrict__ bias, const float* __restrict__ Rsd,
    OUT* __restrict__ C,
    int K, int N, int lda, int ldb,
    size_t aStride, size_t bStride, size_t cStride, size_t rStride,
    float alpha)
{
    extern __shared__ char smem_c[];
    __nv_bfloat16* smemh = (__nv_bfloat16*)smem_c;
    using L = BF16Lay<AROW, BROW>;
    const int bz = blockIdx.z;
    A += aStride * bz; B += bStride * bz; C += cStride * bz;
    const float* R = Rsd ? (Rsd + rStride * bz) : nullptr;
    const int m0 = blockIdx.y * 128, n0 = blockIdx.x * 128;

    const int t = threadIdx.x;
    const int wid = t >> 5;
    const int wm = wid & 3;
    const int wn = wid >> 2;

    using ALay = typename std::conditional<AROW, wmma::row_major, wmma::col_major>::type;
    using BLay = typename std::conditional<BROW, wmma::row_major, wmma::col_major>::type;
    wmma::fragment<wmma::matrix_a, 16, 16, 16, __nv_bfloat16, ALay> af[2];
    wmma::fragment<wmma::matrix_b, 16, 16, 16, __nv_bfloat16, BLay> bf[4];
    wmma::fragment<wmma::accumulator, 16, 16, 16, float> acc[2][4];
#pragma unroll
    for (int i = 0; i < 2; i++)
#pragma unroll
        for (int j = 0; j < 4; j++)
            wmma::fill_fragment(acc[i][j], 0.f);

    auto load_stage = [&](int st, int k0) {
        __nv_bfloat16* As = smemh + st * L::STG;
        __nv_bfloat16* Bs = As + L::ASTG;
#pragma unroll
        for (int c = t; c < 512; c += 256) {
            if (AROW) {
                int m = c >> 2, kk = (c & 3) << 3;
                cp_async16(As + m * L::LDA + kk, A + (size_t)(m0 + m) * lda + k0 + kk);
            } else {
                int k = c >> 4, mm = (c & 15) << 3;
                cp_async16(As + k * L::LDA + mm, A + (size_t)(k0 + k) * lda + m0 + mm);
            }
        }
#pragma unroll
        for (int c = t; c < 512; c += 256) {
            if (BROW) {
                int k = c >> 4, nn = (c & 15) << 3;
                cp_async16(Bs + k * L::LDB + nn, B + (size_t)(k0 + k) * ldb + n0 + nn);
            } else {
                int n = c >> 2, kk = (c & 3) << 3;
                cp_async16(Bs + n * L::LDB + kk, B + (size_t)(n0 + n) * ldb + k0 + kk);
            }
        }
    };

    const int KT = K >> 5;
    load_stage(0, 0);
    cp_commit();

    for (int kt = 0; kt < KT; kt++) {
        if (kt + 1 < KT) load_stage((kt + 1) & 1, (kt + 1) << 5);
        cp_commit();
        cp_wait<1>();
        __syncthreads();

        const __nv_bfloat16* As = smemh + (kt & 1) * L::STG;
        const __nv_bfloat16* Bs = As + L::ASTG;
#pragma unroll
        for (int ks = 0; ks < 32; ks += 16) {
#pragma unroll
            for (int i = 0; i < 2; i++) {
                const __nv_bfloat16* ap = AROW
                    ? As + (wm * 32 + i * 16) * L::LDA + ks
                    : As + ks * L::LDA + (wm * 32 + i * 16);
                wmma::load_matrix_sync(af[i], ap, L::LDA);
            }
#pragma unroll
            for (int j = 0; j < 4; j++) {
                const __nv_bfloat16* bp = BROW
                    ? Bs + ks * L::LDB + (wn * 64 + j * 16)
                    : Bs + (wn * 64 + j * 16) * L::LDB + ks;
                wmma::load_matrix_sync(bf[j], bp, L::LDB);
            }
#pragma unroll
            for (int i = 0; i < 2; i++)
#pragma unroll
                for (int j = 0; j < 4; j++)
                    wmma::mma_sync(acc[i][j], af[i], bf[j], acc[i][j]);
        }
        __syncthreads();
    }

    // ---- epilogue through smem staging (128 x 132 fp32) ----
    float* Csh = (float*)smem_c;
#pragma unroll
    for (int i = 0; i < 2; i++)
#pragma unroll
        for (int j = 0; j < 4; j++)
            wmma::store_matrix_sync(Csh + (wm * 32 + i * 16) * 132 + wn * 64 + j * 16,
                                    acc[i][j], 132, wmma::mem_row_major);
    __syncthreads();

    const int c4 = (t & 31) << 2;
    for (int r = t >> 5; r < 128; r += 8) {
        float4 v = *(const float4*)(Csh + r * 132 + c4);
        const int m = m0 + r;
        float bsv = bias ? bias[m] : 0.f;
        v.x = v.x * alpha + bsv;
        v.y = v.y * alpha + bsv;
        v.z = v.z * alpha + bsv;
        v.w = v.w * alpha + bsv;
        if (R) {
            float4 rv = *(const float4*)(R + (size_t)m * N + n0 + c4);
            v.x += rv.x; v.y += rv.y; v.z += rv.z; v.w += rv.w;
        }
        OUT* cp = C + (size_t)m * N + n0 + c4;
        if (std::is_same<OUT, float>::value) {
            *(float4*)(void*)cp = v;
        } else {
            ushort4 u;
            u.x = __bfloat16_as_ushort(__float2bfloat16(v.x));
            u.y = __bfloat16_as_ushort(__float2bfloat16(v.y));
            u.z = __bfloat16_as_ushort(__float2bfloat16(v.z));
            u.w = __bfloat16_as_ushort(__float2bfloat16(v.w));
            *(ushort4*)(void*)cp = u;
        }
    }
}

// ============================================================
// Softmax (bf16 rows of 4096 -> bf16 attn), fp32 internally
// ============================================================
__global__ void __launch_bounds__(256) softmax_kernel(
    const __nv_bfloat16* __restrict__ S, __nv_bfloat16* __restrict__ Aout)
{
    const __nv_bfloat162* row2 = (const __nv_bfloat162*)(S + (size_t)blockIdx.x * HW);
    __nv_bfloat162* arow2 = (__nv_bfloat162*)(Aout + (size_t)blockIdx.x * HW);
    const int t = threadIdx.x;
    __shared__ float sh[8];

    float m = -1e30f;
    for (int i = t; i < HW / 2; i += 256) {
        float2 f = __bfloat1622float2(row2[i]);
        m = fmaxf(m, fmaxf(f.x, f.y));
    }
    for (int o = 16; o; o >>= 1) m = fmaxf(m, __shfl_xor_sync(0xffffffffu, m, o));
    if ((t & 31) == 0) sh[t >> 5] = m;
    __syncthreads();
    m = sh[0];
#pragma unroll
    for (int i = 1; i < 8; i++) m = fmaxf(m, sh[i]);

    float s = 0.f;
    float ebuf[16];
    for (int i = t, c = 0; i < HW / 2; i += 256, c += 2) {
        float2 f = __bfloat1622float2(row2[i]);
        float e0 = __expf(f.x - m);
        float e1 = __expf(f.y - m);
        ebuf[c] = e0; ebuf[c + 1] = e1;
        s += e0 + e1;
    }
    for (int o = 16; o; o >>= 1) s += __shfl_xor_sync(0xffffffffu, s, o);
    __syncthreads();
    if ((t & 31) == 0) sh[t >> 5] = s;
    __syncthreads();
    s = 0.f;
#pragma unroll
    for (int i = 0; i < 8; i++) s += sh[i];
    float inv = 1.f / s;
    for (int i = t, c = 0; i < HW / 2; i += 256, c += 2)
        arow2[i] = __floats2bfloat162_rn(ebuf[c] * inv, ebuf[c + 1] * inv);
}

// ============================================================
// Launch
// ============================================================
extern "C" void kernel_launch(void* const* d_in, const int* in_sizes, int n_in,
                              void* d_out, int out_size)
{
    const float* x      = (const float*)d_in[0];
    const float* gamma  = (const float*)d_in[1];
    const float* beta   = (const float*)d_in[2];
    const float* qkv_w  = (const float*)d_in[3];
    const float* qkv_b  = (const float*)d_in[4];
    const float* proj_w = (const float*)d_in[5];
    const float* proj_b = (const float*)d_in[6];
    float* out = (float*)d_out;

    __nv_bfloat16 *hn, *qkv, *scores, *attn, *ao, *qw, *pw;
    cudaGetSymbolAddress((void**)&hn, g_hn);
    cudaGetSymbolAddress((void**)&qkv, g_qkv);
    cudaGetSymbolAddress((void**)&scores, g_scores);
    cudaGetSymbolAddress((void**)&attn, g_attn);
    cudaGetSymbolAddress((void**)&ao, g_ao);
    cudaGetSymbolAddress((void**)&qw, g_qw_h);
    cudaGetSymbolAddress((void**)&pw, g_pw_h);

    cudaFuncSetAttribute(gemm_bf16v2<true,  true,  __nv_bfloat16>, cudaFuncAttributeMaxDynamicSharedMemorySize, SMEM_GEMM);
    cudaFuncSetAttribute(gemm_bf16v2<false, true,  __nv_bfloat16>, cudaFuncAttributeMaxDynamicSharedMemorySize, SMEM_GEMM);
    cudaFuncSetAttribute(gemm_bf16v2<true,  false, __nv_bfloat16>, cudaFuncAttributeMaxDynamicSharedMemorySize, SMEM_GEMM);
    cudaFuncSetAttribute(gemm_bf16v2<true,  true,  float>,         cudaFuncAttributeMaxDynamicSharedMemorySize, SMEM_GEMM);

    // Launches 0-2: weight conversions (split so QK lands at ncu -s 5)
    cvt_kernel<<<256, 256>>>(qkv_w, qw, NQKV * CC / 2);
    cvt_kernel<<<256, 256>>>(qkv_w + NQKV * CC / 2, qw + NQKV * CC / 2, NQKV * CC / 2);
    cvt_kernel<<<256, 256>>>(proj_w, pw, CC * CC);

    // 3) GroupNorm -> bf16 hn
    gn_kernel<<<BB * NG, 512>>>(x, gamma, beta, hn);

    // 4) QKV = W_qkv @ hn + b  (bf16 x bf16 -> bf16)
    {
        dim3 grid(HW / 128, NQKV / 128, BB);
        gemm_bf16v2<true, true, __nv_bfloat16><<<grid, 256, SMEM_GEMM>>>(
            qw, hn, qkv_b, nullptr, qkv,
            CC, HW, CC, HW,
            0, (size_t)CC * HW, (size_t)NQKV * HW, 0, 1.f);
    }

    // 5) scores = scale * Q^T K  -> bf16        (ncu samples this launch)
    {
        dim3 grid(HW / 128, HW / 128, BB);
        gemm_bf16v2<false, true, __nv_bfloat16><<<grid, 256, SMEM_GEMM>>>(
            qkv, qkv + (size_t)CC * HW, nullptr, nullptr, scores,
            CC, HW, HW, HW,
            (size_t)NQKV * HW, (size_t)NQKV * HW, (size_t)HW * HW, 0,
            0.04419417382415922f);
    }

    // 6) softmax rows -> bf16
    softmax_kernel<<<BB * HW, 256>>>(scores, attn);

    // 7) attnout = V @ attn^T  -> bf16
    {
        dim3 grid(HW / 128, CC / 128, BB);
        gemm_bf16v2<true, false, __nv_bfloat16><<<grid, 256, SMEM_GEMM>>>(
            qkv + (size_t)2 * CC * HW, attn, nullptr, nullptr, ao,
            HW, HW, HW, HW,
            (size_t)NQKV * HW, (size_t)HW * HW, (size_t)CC * HW, 0, 1.f);
    }

    // 8) out = x + proj_w @ attnout + proj_b  (fp32 out)
    {
        dim3 grid(HW / 128, CC / 128, BB);
        gemm_bf16v2<true, true, float><<<grid, 256, SMEM_GEMM>>>(
            pw, ao, proj_b, x, out,
            CC, HW, CC, HW,
            0, (size_t)CC * HW, (size_t)CC * HW, (size_t)CC * HW, 1.f);
    }
}

// round 9
// speedup vs baseline: 4.5130x; 1.0313x over previous
#include <cuda_runtime.h>
#include <cstdint>
#include <cuda_bf16.h>
#include <mma.h>
#include <math.h>
#include <type_traits>

using namespace nvcuda;

#define BB 2
#define CC 512
#define HW 4096
#define NG 32
#define CPG 16
#define NQKV 1536

// ---- scratch ----
__device__ __align__(256) __nv_bfloat16 g_hn[BB * CC * HW];             // 8 MB
__device__ __align__(256) __nv_bfloat16 g_qkv[BB * NQKV * HW];          // 25 MB
__device__ __align__(256) __nv_bfloat16 g_scores[(size_t)BB * HW * HW]; // 67 MB
__device__ __align__(256) __nv_bfloat16 g_attn[(size_t)BB * HW * HW];   // 67 MB
__device__ __align__(256) __nv_bfloat16 g_ao[BB * CC * HW];             // 8 MB
__device__ __align__(256) __nv_bfloat16 g_qw_h[NQKV * CC];
__device__ __align__(256) __nv_bfloat16 g_pw_h[CC * CC];
__device__ __align__(256) float g_gnstat[BB * NG * 8 * 2];              // partial sums

// ============================================================
// cp.async helpers
// ============================================================
__device__ __forceinline__ void cp_async16(void* sdst, const void* gsrc) {
    unsigned s = (unsigned)__cvta_generic_to_shared(sdst);
    asm volatile("cp.async.ca.shared.global [%0], [%1], 16;\n" :: "r"(s), "l"(gsrc));
}
__device__ __forceinline__ void cp_commit() {
    asm volatile("cp.async.commit_group;\n");
}
template<int N> __device__ __forceinline__ void cp_wait() {
    asm volatile("cp.async.wait_group %0;\n" :: "n"(N));
}

// ---- bf16 GEMM smem pipeline layout ----
template<bool AROW, bool BROW>
struct BF16Lay {
    static const int LDA  = AROW ? 48 : 144;
    static const int LDB  = BROW ? 144 : 48;
    static const int ASTG = AROW ? 128 * 48 : 32 * 144;
    static const int BSTG = BROW ? 32 * 144 : 128 * 48;
    static const int STG  = ASTG + BSTG;
};
static const int SMEM_GEMM = 128 * 132 * 4;   // epilogue staging dominates: 67584 B

// ============================================================
// fp32 -> bf16 conversion (weights)
// ============================================================
__global__ void cvt_kernel(const float* __restrict__ s, __nv_bfloat16* __restrict__ d, int n)
{
    for (int i = blockIdx.x * blockDim.x + threadIdx.x; i < n; i += gridDim.x * blockDim.x)
        d[i] = __float2bfloat16(s[i]);
}

// ============================================================
// GroupNorm phase 1: partial sums. grid = BB*NG*8, block 256.
// Each block: 8192 contiguous floats of one group slice.
// ============================================================
__global__ void __launch_bounds__(256) gn_stats(
    const float* __restrict__ x, float* __restrict__ stat)
{
    const size_t base = (size_t)blockIdx.x * 8192;
    const float4* xp = (const float4*)(x + base);
    float s = 0.f, ss = 0.f;
#pragma unroll
    for (int k = 0; k < 8; k++) {
        float4 v = xp[k * 256 + threadIdx.x];
        s  += v.x + v.y + v.z + v.w;
        ss += v.x * v.x + v.y * v.y + v.z * v.z + v.w * v.w;
    }
    __shared__ float sh_s[8], sh_q[8];
    for (int o = 16; o; o >>= 1) {
        s  += __shfl_down_sync(0xffffffffu, s, o);
        ss += __shfl_down_sync(0xffffffffu, ss, o);
    }
    int warp = threadIdx.x >> 5, lane = threadIdx.x & 31;
    if (lane == 0) { sh_s[warp] = s; sh_q[warp] = ss; }
    __syncthreads();
    if (threadIdx.x == 0) {
        float ts = 0.f, tq = 0.f;
#pragma unroll
        for (int i = 0; i < 8; i++) { ts += sh_s[i]; tq += sh_q[i]; }
        stat[blockIdx.x * 2]     = ts;
        stat[blockIdx.x * 2 + 1] = tq;
    }
}

// ============================================================
// GroupNorm phase 2: apply. grid = BB*CC (one (b,channel) per block), 256 thr.
// ============================================================
__global__ void __launch_bounds__(256) gn_apply(
    const float* __restrict__ x, const float* __restrict__ stat,
    const float* __restrict__ gamma, const float* __restrict__ beta,
    __nv_bfloat16* __restrict__ hn)
{
    const int bc = blockIdx.x;            // 0..1023 = b*512 + ch
    const int ch = bc & (CC - 1);
    const int bg = bc >> 4;               // (b*512+ch)/16 = global group id 0..63
    __shared__ float sh[2];
    if (threadIdx.x == 0) {
        float s = 0.f, q = 0.f;
#pragma unroll
        for (int i = 0; i < 8; i++) {
            s += stat[(bg * 8 + i) * 2];
            q += stat[(bg * 8 + i) * 2 + 1];
        }
        const float inv_n = 1.f / (float)(CPG * HW);
        float mean = s * inv_n;
        float var  = q * inv_n - mean * mean;
        sh[0] = mean;
        sh[1] = rsqrtf(var + 1e-6f);
    }
    __syncthreads();
    const float mean = sh[0], rstd = sh[1];
    const float ga = gamma[ch], be = beta[ch];
    const float a = rstd * ga;
    const float b = be - mean * a;

    const float4* xp = (const float4*)(x + (size_t)bc * HW);
    __nv_bfloat162* op = (__nv_bfloat162*)(g_hn + 0) + 0;  // placate compiler; real ptr below
    __nv_bfloat162* o2 = (__nv_bfloat162*)(hn + (size_t)bc * HW);
    (void)op;
#pragma unroll
    for (int k = 0; k < 4; k++) {
        int i = k * 256 + threadIdx.x;
        float4 v = xp[i];
        o2[2 * i]     = __floats2bfloat162_rn(v.x * a + b, v.y * a + b);
        o2[2 * i + 1] = __floats2bfloat162_rn(v.z * a + b, v.w * a + b);
    }
}

// ============================================================
// BF16 tensor-core GEMM: C = alpha*op(A)*op(B) (+bias)(+resid fp32)
// ============================================================
template<bool AROW, bool BROW, typename OUT>
__global__ void __launch_bounds__(256) gemm_bf16v2(
    const __nv_bfloat16* __restrict__ A, const __nv_bfloat16* __restrict__ B,
    const float* __restrict__ bias, const float* __restrict__ Rsd,
    OUT* __restrict__ C,
    int K, int N, int lda, int ldb,
    size_t aStride, size_t bStride, size_t cStride, size_t rStride,
    float alpha)
{
    extern __shared__ char smem_c[];
    __nv_bfloat16* smemh = (__nv_bfloat16*)smem_c;
    using L = BF16Lay<AROW, BROW>;
    const int bz = blockIdx.z;
    A += aStride * bz; B += bStride * bz; C += cStride * bz;
    const float* R = Rsd ? (Rsd + rStride * bz) : nullptr;
    const int m0 = blockIdx.y * 128, n0 = blockIdx.x * 128;

    const int t = threadIdx.x;
    const int wid = t >> 5;
    const int wm = wid & 3;
    const int wn = wid >> 2;

    using ALay = typename std::conditional<AROW, wmma::row_major, wmma::col_major>::type;
    using BLay = typename std::conditional<BROW, wmma::row_major, wmma::col_major>::type;
    wmma::fragment<wmma::matrix_a, 16, 16, 16, __nv_bfloat16, ALay> af[2];
    wmma::fragment<wmma::matrix_b, 16, 16, 16, __nv_bfloat16, BLay> bf[4];
    wmma::fragment<wmma::accumulator, 16, 16, 16, float> acc[2][4];
#pragma unroll
    for (int i = 0; i < 2; i++)
#pragma unroll
        for (int j = 0; j < 4; j++)
            wmma::fill_fragment(acc[i][j], 0.f);

    auto load_stage = [&](int st, int k0) {
        __nv_bfloat16* As = smemh + st * L::STG;
        __nv_bfloat16* Bs = As + L::ASTG;
#pragma unroll
        for (int c = t; c < 512; c += 256) {
            if (AROW) {
                int m = c >> 2, kk = (c & 3) << 3;
                cp_async16(As + m * L::LDA + kk, A + (size_t)(m0 + m) * lda + k0 + kk);
            } else {
                int k = c >> 4, mm = (c & 15) << 3;
                cp_async16(As + k * L::LDA + mm, A + (size_t)(k0 + k) * lda + m0 + mm);
            }
        }
#pragma unroll
        for (int c = t; c < 512; c += 256) {
            if (BROW) {
                int k = c >> 4, nn = (c & 15) << 3;
                cp_async16(Bs + k * L::LDB + nn, B + (size_t)(k0 + k) * ldb + n0 + nn);
            } else {
                int n = c >> 2, kk = (c & 3) << 3;
                cp_async16(Bs + n * L::LDB + kk, B + (size_t)(n0 + n) * ldb + k0 + kk);
            }
        }
    };

    const int KT = K >> 5;
    load_stage(0, 0);
    cp_commit();

    for (int kt = 0; kt < KT; kt++) {
        if (kt + 1 < KT) load_stage((kt + 1) & 1, (kt + 1) << 5);
        cp_commit();
        cp_wait<1>();
        __syncthreads();

        const __nv_bfloat16* As = smemh + (kt & 1) * L::STG;
        const __nv_bfloat16* Bs = As + L::ASTG;
#pragma unroll
        for (int ks = 0; ks < 32; ks += 16) {
#pragma unroll
            for (int i = 0; i < 2; i++) {
                const __nv_bfloat16* ap = AROW
                    ? As + (wm * 32 + i * 16) * L::LDA + ks
                    : As + ks * L::LDA + (wm * 32 + i * 16);
                wmma::load_matrix_sync(af[i], ap, L::LDA);
            }
#pragma unroll
            for (int j = 0; j < 4; j++) {
                const __nv_bfloat16* bp = BROW
                    ? Bs + ks * L::LDB + (wn * 64 + j * 16)
                    : Bs + (wn * 64 + j * 16) * L::LDB + ks;
                wmma::load_matrix_sync(bf[j], bp, L::LDB);
            }
#pragma unroll
            for (int i = 0; i < 2; i++)
#pragma unroll
                for (int j = 0; j < 4; j++)
                    wmma::mma_sync(acc[i][j], af[i], bf[j], acc[i][j]);
        }
        __syncthreads();
    }

    // ---- epilogue through smem staging (128 x 132 fp32) ----
    float* Csh = (float*)smem_c;
#pragma unroll
    for (int i = 0; i < 2; i++)
#pragma unroll
        for (int j = 0; j < 4; j++)
            wmma::store_matrix_sync(Csh + (wm * 32 + i * 16) * 132 + wn * 64 + j * 16,
                                    acc[i][j], 132, wmma::mem_row_major);
    __syncthreads();

    const int c4 = (t & 31) << 2;
    for (int r = t >> 5; r < 128; r += 8) {
        float4 v = *(const float4*)(Csh + r * 132 + c4);
        const int m = m0 + r;
        float bsv = bias ? bias[m] : 0.f;
        v.x = v.x * alpha + bsv;
        v.y = v.y * alpha + bsv;
        v.z = v.z * alpha + bsv;
        v.w = v.w * alpha + bsv;
        if (R) {
            float4 rv = *(const float4*)(R + (size_t)m * N + n0 + c4);
            v.x += rv.x; v.y += rv.y; v.z += rv.z; v.w += rv.w;
        }
        OUT* cp = C + (size_t)m * N + n0 + c4;
        if (std::is_same<OUT, float>::value) {
            *(float4*)(void*)cp = v;
        } else {
            ushort4 u;
            u.x = __bfloat16_as_ushort(__float2bfloat16(v.x));
            u.y = __bfloat16_as_ushort(__float2bfloat16(v.y));
            u.z = __bfloat16_as_ushort(__float2bfloat16(v.z));
            u.w = __bfloat16_as_ushort(__float2bfloat16(v.w));
            *(ushort4*)(void*)cp = u;
        }
    }
}

// ============================================================
// Softmax (bf16 rows of 4096 -> bf16 attn), fp32 internally
// ============================================================
__global__ void __launch_bounds__(256) softmax_kernel(
    const __nv_bfloat16* __restrict__ S, __nv_bfloat16* __restrict__ Aout)
{
    const __nv_bfloat162* row2 = (const __nv_bfloat162*)(S + (size_t)blockIdx.x * HW);
    __nv_bfloat162* arow2 = (__nv_bfloat162*)(Aout + (size_t)blockIdx.x * HW);
    const int t = threadIdx.x;
    __shared__ float sh[8];

    float m = -1e30f;
    for (int i = t; i < HW / 2; i += 256) {
        float2 f = __bfloat1622float2(row2[i]);
        m = fmaxf(m, fmaxf(f.x, f.y));
    }
    for (int o = 16; o; o >>= 1) m = fmaxf(m, __shfl_xor_sync(0xffffffffu, m, o));
    if ((t & 31) == 0) sh[t >> 5] = m;
    __syncthreads();
    m = sh[0];
#pragma unroll
    for (int i = 1; i < 8; i++) m = fmaxf(m, sh[i]);

    float s = 0.f;
    float ebuf[16];
    for (int i = t, c = 0; i < HW / 2; i += 256, c += 2) {
        float2 f = __bfloat1622float2(row2[i]);
        float e0 = __expf(f.x - m);
        float e1 = __expf(f.y - m);
        ebuf[c] = e0; ebuf[c + 1] = e1;
        s += e0 + e1;
    }
    for (int o = 16; o; o >>= 1) s += __shfl_xor_sync(0xffffffffu, s, o);
    __syncthreads();
    if ((t & 31) == 0) sh[t >> 5] = s;
    __syncthreads();
    s = 0.f;
#pragma unroll
    for (int i = 0; i < 8; i++) s += sh[i];
    float inv = 1.f / s;
    for (int i = t, c = 0; i < HW / 2; i += 256, c += 2)
        arow2[i] = __floats2bfloat162_rn(ebuf[c] * inv, ebuf[c + 1] * inv);
}

// ============================================================
// Launch
// ============================================================
extern "C" void kernel_launch(void* const* d_in, const int* in_sizes, int n_in,
                              void* d_out, int out_size)
{
    const float* x      = (const float*)d_in[0];
    const float* gamma  = (const float*)d_in[1];
    const float* beta   = (const float*)d_in[2];
    const float* qkv_w  = (const float*)d_in[3];
    const float* qkv_b  = (const float*)d_in[4];
    const float* proj_w = (const float*)d_in[5];
    const float* proj_b = (const float*)d_in[6];
    float* out = (float*)d_out;

    __nv_bfloat16 *hn, *qkv, *scores, *attn, *ao, *qw, *pw;
    float* stat;
    cudaGetSymbolAddress((void**)&hn, g_hn);
    cudaGetSymbolAddress((void**)&qkv, g_qkv);
    cudaGetSymbolAddress((void**)&scores, g_scores);
    cudaGetSymbolAddress((void**)&attn, g_attn);
    cudaGetSymbolAddress((void**)&ao, g_ao);
    cudaGetSymbolAddress((void**)&qw, g_qw_h);
    cudaGetSymbolAddress((void**)&pw, g_pw_h);
    cudaGetSymbolAddress((void**)&stat, g_gnstat);

    cudaFuncSetAttribute(gemm_bf16v2<true,  true,  __nv_bfloat16>, cudaFuncAttributeMaxDynamicSharedMemorySize, SMEM_GEMM);
    cudaFuncSetAttribute(gemm_bf16v2<false, true,  __nv_bfloat16>, cudaFuncAttributeMaxDynamicSharedMemorySize, SMEM_GEMM);
    cudaFuncSetAttribute(gemm_bf16v2<true,  false, __nv_bfloat16>, cudaFuncAttributeMaxDynamicSharedMemorySize, SMEM_GEMM);
    cudaFuncSetAttribute(gemm_bf16v2<true,  true,  float>,         cudaFuncAttributeMaxDynamicSharedMemorySize, SMEM_GEMM);

    // 0-1) weight conversions
    cvt_kernel<<<264, 256>>>(qkv_w, qw, NQKV * CC);
    cvt_kernel<<<264, 256>>>(proj_w, pw, CC * CC);

    // 2) GroupNorm stats (full-chip)
    gn_stats<<<BB * NG * 8, 256>>>(x, stat);

    // 3) GroupNorm apply -> bf16 hn (full-chip)
    gn_apply<<<BB * CC, 256>>>(x, stat, gamma, beta, hn);

    // 4) QKV = W_qkv @ hn + b  (bf16 x bf16 -> bf16)
    {
        dim3 grid(HW / 128, NQKV / 128, BB);
        gemm_bf16v2<true, true, __nv_bfloat16><<<grid, 256, SMEM_GEMM>>>(
            qw, hn, qkv_b, nullptr, qkv,
            CC, HW, CC, HW,
            0, (size_t)CC * HW, (size_t)NQKV * HW, 0, 1.f);
    }

    // 5) scores = scale * Q^T K  -> bf16    (ncu -s 5 samples this launch)
    {
        dim3 grid(HW / 128, HW / 128, BB);
        gemm_bf16v2<false, true, __nv_bfloat16><<<grid, 256, SMEM_GEMM>>>(
            qkv, qkv + (size_t)CC * HW, nullptr, nullptr, scores,
            CC, HW, HW, HW,
            (size_t)NQKV * HW, (size_t)NQKV * HW, (size_t)HW * HW, 0,
            0.04419417382415922f);
    }

    // 6) softmax rows -> bf16
    softmax_kernel<<<BB * HW, 256>>>(scores, attn);

    // 7) attnout = V @ attn^T  -> bf16
    {
        dim3 grid(HW / 128, CC / 128, BB);
        gemm_bf16v2<true, false, __nv_bfloat16><<<grid, 256, SMEM_GEMM>>>(
            qkv + (size_t)2 * CC * HW, attn, nullptr, nullptr, ao,
            HW, HW, HW, HW,
            (size_t)NQKV * HW, (size_t)HW * HW, (size_t)CC * HW, 0, 1.f);
    }

    // 8) out = x + proj_w @ attnout + proj_b  (fp32 out)
    {
        dim3 grid(HW / 128, CC / 128, BB);
        gemm_bf16v2<true, true, float><<<grid, 256, SMEM_GEMM>>>(
            pw, ao, proj_b, x, out,
            CC, HW, CC, HW,
            0, (size_t)CC * HW, (size_t)CC * HW, (size_t)CC * HW, 1.f);
    }
}

// round 10
// speedup vs baseline: 4.5380x; 1.0056x over previous
#include <cuda_runtime.h>
#include <cstdint>
#include <cuda_bf16.h>
#include <mma.h>
#include <math.h>
#include <type_traits>

using namespace nvcuda;

#define BB 2
#define CC 512
#define HW 4096
#define NG 32
#define CPG 16
#define NQKV 1536

// ---- scratch ----
__device__ __align__(256) __nv_bfloat16 g_hn[BB * CC * HW];             // 8 MB
__device__ __align__(256) __nv_bfloat16 g_qkv[BB * NQKV * HW];          // 25 MB
__device__ __align__(256) __nv_bfloat16 g_scores[(size_t)BB * HW * HW]; // 67 MB
__device__ __align__(256) __nv_bfloat16 g_attn[(size_t)BB * HW * HW];   // 67 MB
__device__ __align__(256) __nv_bfloat16 g_ao[BB * CC * HW];             // 8 MB
__device__ __align__(256) __nv_bfloat16 g_qw_h[NQKV * CC];
__device__ __align__(256) __nv_bfloat16 g_pw_h[CC * CC];
__device__ __align__(256) float g_gnstat[BB * NG * 8 * 2];

// ============================================================
// cp.async helpers
// ============================================================
__device__ __forceinline__ void cp_async16(void* sdst, const void* gsrc) {
    unsigned s = (unsigned)__cvta_generic_to_shared(sdst);
    asm volatile("cp.async.ca.shared.global [%0], [%1], 16;\n" :: "r"(s), "l"(gsrc));
}
__device__ __forceinline__ void cp_commit() {
    asm volatile("cp.async.commit_group;\n");
}
template<int N> __device__ __forceinline__ void cp_wait() {
    asm volatile("cp.async.wait_group %0;\n" :: "n"(N));
}

// ---- bf16 GEMM smem layout: 256x128 block tile, BK=32, 2 stages ----
template<bool AROW, bool BROW>
struct BigLay {
    static const int LDA  = AROW ? 48 : 264;           // elems
    static const int LDB  = BROW ? 144 : 48;
    static const int ASTG = AROW ? 256 * 48 : 32 * 264;
    static const int BSTG = BROW ? 32 * 144 : 128 * 48;
    static const int STG  = ASTG + BSTG;
    static const int PIPE = 2 * STG * 2;               // bytes
    static const int BYTES = (PIPE > 67584) ? PIPE : 67584;   // vs epilogue staging
};

// ============================================================
// fp32 -> bf16 conversion (weights)
// ============================================================
__global__ void cvt_kernel(const float* __restrict__ s, __nv_bfloat16* __restrict__ d, int n)
{
    for (int i = blockIdx.x * blockDim.x + threadIdx.x; i < n; i += gridDim.x * blockDim.x)
        d[i] = __float2bfloat16(s[i]);
}

// ============================================================
// GroupNorm phase 1: partial sums. grid = BB*NG*8, block 256.
// ============================================================
__global__ void __launch_bounds__(256) gn_stats(
    const float* __restrict__ x, float* __restrict__ stat)
{
    const size_t base = (size_t)blockIdx.x * 8192;
    const float4* xp = (const float4*)(x + base);
    float s = 0.f, ss = 0.f;
#pragma unroll
    for (int k = 0; k < 8; k++) {
        float4 v = xp[k * 256 + threadIdx.x];
        s  += v.x + v.y + v.z + v.w;
        ss += v.x * v.x + v.y * v.y + v.z * v.z + v.w * v.w;
    }
    __shared__ float sh_s[8], sh_q[8];
    for (int o = 16; o; o >>= 1) {
        s  += __shfl_down_sync(0xffffffffu, s, o);
        ss += __shfl_down_sync(0xffffffffu, ss, o);
    }
    int warp = threadIdx.x >> 5, lane = threadIdx.x & 31;
    if (lane == 0) { sh_s[warp] = s; sh_q[warp] = ss; }
    __syncthreads();
    if (threadIdx.x == 0) {
        float ts = 0.f, tq = 0.f;
#pragma unroll
        for (int i = 0; i < 8; i++) { ts += sh_s[i]; tq += sh_q[i]; }
        stat[blockIdx.x * 2]     = ts;
        stat[blockIdx.x * 2 + 1] = tq;
    }
}

// ============================================================
// GroupNorm phase 2: apply. grid = BB*CC, 256 thr.
// ============================================================
__global__ void __launch_bounds__(256) gn_apply(
    const float* __restrict__ x, const float* __restrict__ stat,
    const float* __restrict__ gamma, const float* __restrict__ beta,
    __nv_bfloat16* __restrict__ hn)
{
    const int bc = blockIdx.x;
    const int ch = bc & (CC - 1);
    const int bg = bc >> 4;
    __shared__ float sh[2];
    if (threadIdx.x == 0) {
        float s = 0.f, q = 0.f;
#pragma unroll
        for (int i = 0; i < 8; i++) {
            s += stat[(bg * 8 + i) * 2];
            q += stat[(bg * 8 + i) * 2 + 1];
        }
        const float inv_n = 1.f / (float)(CPG * HW);
        float mean = s * inv_n;
        float var  = q * inv_n - mean * mean;
        sh[0] = mean;
        sh[1] = rsqrtf(var + 1e-6f);
    }
    __syncthreads();
    const float mean = sh[0], rstd = sh[1];
    const float a = rstd * gamma[ch];
    const float b = beta[ch] - mean * a;

    const float4* xp = (const float4*)(x + (size_t)bc * HW);
    __nv_bfloat162* o2 = (__nv_bfloat162*)(hn + (size_t)bc * HW);
#pragma unroll
    for (int k = 0; k < 4; k++) {
        int i = k * 256 + threadIdx.x;
        float4 v = xp[i];
        o2[2 * i]     = __floats2bfloat162_rn(v.x * a + b, v.y * a + b);
        o2[2 * i + 1] = __floats2bfloat162_rn(v.z * a + b, v.w * a + b);
    }
}

// ============================================================
// BF16 tensor-core GEMM, 256x128 block tile, warp tile 64x64.
// C = alpha*op(A)*op(B) (+bias)(+resid fp32)
// ============================================================
template<bool AROW, bool BROW, typename OUT>
__global__ void __launch_bounds__(256) gemm_big(
    const __nv_bfloat16* __restrict__ A, const __nv_bfloat16* __restrict__ B,
    const float* __restrict__ bias, const float* __restrict__ Rsd,
    OUT* __restrict__ C,
    int K, int N, int lda, int ldb,
    size_t aStride, size_t bStride, size_t cStride, size_t rStride,
    float alpha)
{
    extern __shared__ char smem_c[];
    __nv_bfloat16* smemh = (__nv_bfloat16*)smem_c;
    using L = BigLay<AROW, BROW>;
    const int bz = blockIdx.z;
    A += aStride * bz; B += bStride * bz; C += cStride * bz;
    const float* R = Rsd ? (Rsd + rStride * bz) : nullptr;
    const int m0 = blockIdx.y * 256, n0 = blockIdx.x * 128;

    const int t = threadIdx.x;
    const int wid = t >> 5;
    const int wm = wid & 3;          // 4 warps x 64 rows
    const int wn = wid >> 2;         // 2 warps x 64 cols

    using ALay = typename std::conditional<AROW, wmma::row_major, wmma::col_major>::type;
    using BLay = typename std::conditional<BROW, wmma::row_major, wmma::col_major>::type;
    wmma::fragment<wmma::matrix_a, 16, 16, 16, __nv_bfloat16, ALay> af[4];
    wmma::fragment<wmma::matrix_b, 16, 16, 16, __nv_bfloat16, BLay> bf[4];
    wmma::fragment<wmma::accumulator, 16, 16, 16, float> acc[4][4];
#pragma unroll
    for (int i = 0; i < 4; i++)
#pragma unroll
        for (int j = 0; j < 4; j++)
            wmma::fill_fragment(acc[i][j], 0.f);

    auto load_stage = [&](int st, int k0) {
        __nv_bfloat16* As = smemh + st * L::STG;
        __nv_bfloat16* Bs = As + L::ASTG;
#pragma unroll
        for (int c = t; c < 1024; c += 256) {
            if (AROW) {                    // 256 rows x 32 k
                int m = c >> 2, kk = (c & 3) << 3;
                cp_async16(As + m * L::LDA + kk, A + (size_t)(m0 + m) * lda + k0 + kk);
            } else {                       // 32 k-rows x 256 m
                int k = c >> 5, mm = (c & 31) << 3;
                cp_async16(As + k * L::LDA + mm, A + (size_t)(k0 + k) * lda + m0 + mm);
            }
        }
#pragma unroll
        for (int c = t; c < 512; c += 256) {
            if (BROW) {                    // 32 k-rows x 128 n
                int k = c >> 4, nn = (c & 15) << 3;
                cp_async16(Bs + k * L::LDB + nn, B + (size_t)(k0 + k) * ldb + n0 + nn);
            } else {                       // 128 n-rows x 32 k
                int n = c >> 2, kk = (c & 3) << 3;
                cp_async16(Bs + n * L::LDB + kk, B + (size_t)(n0 + n) * ldb + k0 + kk);
            }
        }
    };

    const int KT = K >> 5;
    load_stage(0, 0);
    cp_commit();

    for (int kt = 0; kt < KT; kt++) {
        if (kt + 1 < KT) load_stage((kt + 1) & 1, (kt + 1) << 5);
        cp_commit();
        cp_wait<1>();
        __syncthreads();

        const __nv_bfloat16* As = smemh + (kt & 1) * L::STG;
        const __nv_bfloat16* Bs = As + L::ASTG;
#pragma unroll
        for (int ks = 0; ks < 32; ks += 16) {
#pragma unroll
            for (int i = 0; i < 4; i++) {
                const __nv_bfloat16* ap = AROW
                    ? As + (wm * 64 + i * 16) * L::LDA + ks
                    : As + ks * L::LDA + (wm * 64 + i * 16);
                wmma::load_matrix_sync(af[i], ap, L::LDA);
            }
#pragma unroll
            for (int j = 0; j < 4; j++) {
                const __nv_bfloat16* bp = BROW
                    ? Bs + ks * L::LDB + (wn * 64 + j * 16)
                    : Bs + (wn * 64 + j * 16) * L::LDB + ks;
                wmma::load_matrix_sync(bf[j], bp, L::LDB);
            }
#pragma unroll
            for (int i = 0; i < 4; i++)
#pragma unroll
                for (int j = 0; j < 4; j++)
                    wmma::mma_sync(acc[i][j], af[i], bf[j], acc[i][j]);
        }
        __syncthreads();
    }

    // ---- epilogue: two 128-row halves through 128x132 fp32 staging ----
    float* Csh = (float*)smem_c;
#pragma unroll
    for (int h = 0; h < 2; h++) {
        if ((wm >> 1) == h) {
#pragma unroll
            for (int i = 0; i < 4; i++)
#pragma unroll
                for (int j = 0; j < 4; j++)
                    wmma::store_matrix_sync(
                        Csh + ((wm & 1) * 64 + i * 16) * 132 + wn * 64 + j * 16,
                        acc[i][j], 132, wmma::mem_row_major);
        }
        __syncthreads();

        const int c4 = (t & 31) << 2;
        for (int r = t >> 5; r < 128; r += 8) {
            float4 v = *(const float4*)(Csh + r * 132 + c4);
            const int m = m0 + h * 128 + r;
            float bsv = bias ? bias[m] : 0.f;
            v.x = v.x * alpha + bsv;
            v.y = v.y * alpha + bsv;
            v.z = v.z * alpha + bsv;
            v.w = v.w * alpha + bsv;
            if (R) {
                float4 rv = *(const float4*)(R + (size_t)m * N + n0 + c4);
                v.x += rv.x; v.y += rv.y; v.z += rv.z; v.w += rv.w;
            }
            OUT* cp = C + (size_t)m * N + n0 + c4;
            if (std::is_same<OUT, float>::value) {
                *(float4*)(void*)cp = v;
            } else {
                ushort4 u;
                u.x = __bfloat16_as_ushort(__float2bfloat16(v.x));
                u.y = __bfloat16_as_ushort(__float2bfloat16(v.y));
                u.z = __bfloat16_as_ushort(__float2bfloat16(v.z));
                u.w = __bfloat16_as_ushort(__float2bfloat16(v.w));
                *(ushort4*)(void*)cp = u;
            }
        }
        __syncthreads();
    }
}

// ============================================================
// Softmax (bf16 rows of 4096 -> bf16 attn), fp32 internally
// ============================================================
__global__ void __launch_bounds__(256) softmax_kernel(
    const __nv_bfloat16* __restrict__ S, __nv_bfloat16* __restrict__ Aout)
{
    const __nv_bfloat162* row2 = (const __nv_bfloat162*)(S + (size_t)blockIdx.x * HW);
    __nv_bfloat162* arow2 = (__nv_bfloat162*)(Aout + (size_t)blockIdx.x * HW);
    const int t = threadIdx.x;
    __shared__ float sh[8];

    float m = -1e30f;
    for (int i = t; i < HW / 2; i += 256) {
        float2 f = __bfloat1622float2(row2[i]);
        m = fmaxf(m, fmaxf(f.x, f.y));
    }
    for (int o = 16; o; o >>= 1) m = fmaxf(m, __shfl_xor_sync(0xffffffffu, m, o));
    if ((t & 31) == 0) sh[t >> 5] = m;
    __syncthreads();
    m = sh[0];
#pragma unroll
    for (int i = 1; i < 8; i++) m = fmaxf(m, sh[i]);

    float s = 0.f;
    float ebuf[16];
    for (int i = t, c = 0; i < HW / 2; i += 256, c += 2) {
        float2 f = __bfloat1622float2(row2[i]);
        float e0 = __expf(f.x - m);
        float e1 = __expf(f.y - m);
        ebuf[c] = e0; ebuf[c + 1] = e1;
        s += e0 + e1;
    }
    for (int o = 16; o; o >>= 1) s += __shfl_xor_sync(0xffffffffu, s, o);
    __syncthreads();
    if ((t & 31) == 0) sh[t >> 5] = s;
    __syncthreads();
    s = 0.f;
#pragma unroll
    for (int i = 0; i < 8; i++) s += sh[i];
    float inv = 1.f / s;
    for (int i = t, c = 0; i < HW / 2; i += 256, c += 2)
        arow2[i] = __floats2bfloat162_rn(ebuf[c] * inv, ebuf[c + 1] * inv);
}

// ============================================================
// Launch
// ============================================================
extern "C" void kernel_launch(void* const* d_in, const int* in_sizes, int n_in,
                              void* d_out, int out_size)
{
    const float* x      = (const float*)d_in[0];
    const float* gamma  = (const float*)d_in[1];
    const float* beta   = (const float*)d_in[2];
    const float* qkv_w  = (const float*)d_in[3];
    const float* qkv_b  = (const float*)d_in[4];
    const float* proj_w = (const float*)d_in[5];
    const float* proj_b = (const float*)d_in[6];
    float* out = (float*)d_out;

    __nv_bfloat16 *hn, *qkv, *scores, *attn, *ao, *qw, *pw;
    float* stat;
    cudaGetSymbolAddress((void**)&hn, g_hn);
    cudaGetSymbolAddress((void**)&qkv, g_qkv);
    cudaGetSymbolAddress((void**)&scores, g_scores);
    cudaGetSymbolAddress((void**)&attn, g_attn);
    cudaGetSymbolAddress((void**)&ao, g_ao);
    cudaGetSymbolAddress((void**)&qw, g_qw_h);
    cudaGetSymbolAddress((void**)&pw, g_pw_h);
    cudaGetSymbolAddress((void**)&stat, g_gnstat);

    cudaFuncSetAttribute(gemm_big<true,  true,  __nv_bfloat16>, cudaFuncAttributeMaxDynamicSharedMemorySize, BigLay<true,  true >::BYTES);
    cudaFuncSetAttribute(gemm_big<false, true,  __nv_bfloat16>, cudaFuncAttributeMaxDynamicSharedMemorySize, BigLay<false, true >::BYTES);
    cudaFuncSetAttribute(gemm_big<true,  false, __nv_bfloat16>, cudaFuncAttributeMaxDynamicSharedMemorySize, BigLay<true,  false>::BYTES);
    cudaFuncSetAttribute(gemm_big<true,  true,  float>,         cudaFuncAttributeMaxDynamicSharedMemorySize, BigLay<true,  true >::BYTES);

    // 0-1) weight conversions
    cvt_kernel<<<264, 256>>>(qkv_w, qw, NQKV * CC);
    cvt_kernel<<<264, 256>>>(proj_w, pw, CC * CC);

    // 2) GroupNorm stats
    gn_stats<<<BB * NG * 8, 256>>>(x, stat);

    // 3) GroupNorm apply -> bf16 hn
    gn_apply<<<BB * CC, 256>>>(x, stat, gamma, beta, hn);

    // 4) QKV = W_qkv @ hn + b
    {
        dim3 grid(HW / 128, NQKV / 256, BB);
        gemm_big<true, true, __nv_bfloat16><<<grid, 256, BigLay<true, true>::BYTES>>>(
            qw, hn, qkv_b, nullptr, qkv,
            CC, HW, CC, HW,
            0, (size_t)CC * HW, (size_t)NQKV * HW, 0, 1.f);
    }

    // 5) scores = scale * Q^T K  (ncu -s 5 samples this)
    {
        dim3 grid(HW / 128, HW / 256, BB);
        gemm_big<false, true, __nv_bfloat16><<<grid, 256, BigLay<false, true>::BYTES>>>(
            qkv, qkv + (size_t)CC * HW, nullptr, nullptr, scores,
            CC, HW, HW, HW,
            (size_t)NQKV * HW, (size_t)NQKV * HW, (size_t)HW * HW, 0,
            0.04419417382415922f);
    }

    // 6) softmax rows -> bf16
    softmax_kernel<<<BB * HW, 256>>>(scores, attn);

    // 7) attnout = V @ attn^T
    {
        dim3 grid(HW / 128, CC / 256, BB);
        gemm_big<true, false, __nv_bfloat16><<<grid, 256, BigLay<true, false>::BYTES>>>(
            qkv + (size_t)2 * CC * HW, attn, nullptr, nullptr, ao,
            HW, HW, HW, HW,
            (size_t)NQKV * HW, (size_t)HW * HW, (size_t)CC * HW, 0, 1.f);
    }

    // 8) out = x + proj_w @ attnout + proj_b
    {
        dim3 grid(HW / 128, CC / 256, BB);
        gemm_big<true, true, float><<<grid, 256, BigLay<true, true>::BYTES>>>(
            pw, ao, proj_b, x, out,
            CC, HW, CC, HW,
            0, (size_t)CC * HW, (size_t)CC * HW, (size_t)CC * HW, 1.f);
    }
}

// round 11
// speedup vs baseline: 4.7833x; 1.0540x over previous
#include <cuda_runtime.h>
#include <cstdint>
#include <cuda_bf16.h>
#include <mma.h>
#include <math.h>
#include <type_traits>

using namespace nvcuda;

#define BB 2
#define CC 512
#define HW 4096
#define NG 32
#define CPG 16
#define NQKV 1536

// ---- scratch ----
__device__ __align__(256) __nv_bfloat16 g_hn[BB * CC * HW];             // 8 MB
__device__ __align__(256) __nv_bfloat16 g_qkv[BB * NQKV * HW];          // 25 MB
__device__ __align__(256) __nv_bfloat16 g_scores[(size_t)BB * HW * HW]; // 67 MB
__device__ __align__(256) __nv_bfloat16 g_attn[(size_t)BB * HW * HW];   // 67 MB
__device__ __align__(256) __nv_bfloat16 g_ao[BB * CC * HW];             // 8 MB
__device__ __align__(256) __nv_bfloat16 g_qw_h[NQKV * CC];
__device__ __align__(256) __nv_bfloat16 g_pw_h[CC * CC];
__device__ __align__(256) float g_gnstat[BB * NG * 8 * 2];

// ============================================================
// cp.async helpers
// ============================================================
__device__ __forceinline__ void cp_async16(void* sdst, const void* gsrc) {
    unsigned s = (unsigned)__cvta_generic_to_shared(sdst);
    asm volatile("cp.async.ca.shared.global [%0], [%1], 16;\n" :: "r"(s), "l"(gsrc));
}
__device__ __forceinline__ void cp_commit() {
    asm volatile("cp.async.commit_group;\n");
}
template<int N> __device__ __forceinline__ void cp_wait() {
    asm volatile("cp.async.wait_group %0;\n" :: "n"(N));
}

// ---- bf16 GEMM smem layout: 256x128 block tile, BK=32, 3 stages ----
template<bool AROW, bool BROW>
struct BigLay {
    static const int LDA  = AROW ? 48 : 264;           // elems
    static const int LDB  = BROW ? 144 : 48;
    static const int ASTG = AROW ? 256 * 48 : 32 * 264;
    static const int BSTG = BROW ? 32 * 144 : 128 * 48;
    static const int STG  = ASTG + BSTG;
    static const int PIPE = 3 * STG * 2;               // bytes, 3 stages
    static const int BYTES = (PIPE > 67584) ? PIPE : 67584;   // vs epilogue staging
};

// ============================================================
// fp32 -> bf16 conversion (weights)
// ============================================================
__global__ void cvt_kernel(const float* __restrict__ s, __nv_bfloat16* __restrict__ d, int n)
{
    for (int i = blockIdx.x * blockDim.x + threadIdx.x; i < n; i += gridDim.x * blockDim.x)
        d[i] = __float2bfloat16(s[i]);
}

// ============================================================
// GroupNorm phase 1: partial sums. grid = BB*NG*8, block 256.
// ============================================================
__global__ void __launch_bounds__(256) gn_stats(
    const float* __restrict__ x, float* __restrict__ stat)
{
    const size_t base = (size_t)blockIdx.x * 8192;
    const float4* xp = (const float4*)(x + base);
    float s = 0.f, ss = 0.f;
#pragma unroll
    for (int k = 0; k < 8; k++) {
        float4 v = xp[k * 256 + threadIdx.x];
        s  += v.x + v.y + v.z + v.w;
        ss += v.x * v.x + v.y * v.y + v.z * v.z + v.w * v.w;
    }
    __shared__ float sh_s[8], sh_q[8];
    for (int o = 16; o; o >>= 1) {
        s  += __shfl_down_sync(0xffffffffu, s, o);
        ss += __shfl_down_sync(0xffffffffu, ss, o);
    }
    int warp = threadIdx.x >> 5, lane = threadIdx.x & 31;
    if (lane == 0) { sh_s[warp] = s; sh_q[warp] = ss; }
    __syncthreads();
    if (threadIdx.x == 0) {
        float ts = 0.f, tq = 0.f;
#pragma unroll
        for (int i = 0; i < 8; i++) { ts += sh_s[i]; tq += sh_q[i]; }
        stat[blockIdx.x * 2]     = ts;
        stat[blockIdx.x * 2 + 1] = tq;
    }
}

// ============================================================
// GroupNorm phase 2: apply. grid = BB*CC, 256 thr.
// ============================================================
__global__ void __launch_bounds__(256) gn_apply(
    const float* __restrict__ x, const float* __restrict__ stat,
    const float* __restrict__ gamma, const float* __restrict__ beta,
    __nv_bfloat16* __restrict__ hn)
{
    const int bc = blockIdx.x;
    const int ch = bc & (CC - 1);
    const int bg = bc >> 4;
    __shared__ float sh[2];
    if (threadIdx.x == 0) {
        float s = 0.f, q = 0.f;
#pragma unroll
        for (int i = 0; i < 8; i++) {
            s += stat[(bg * 8 + i) * 2];
            q += stat[(bg * 8 + i) * 2 + 1];
        }
        const float inv_n = 1.f / (float)(CPG * HW);
        float mean = s * inv_n;
        float var  = q * inv_n - mean * mean;
        sh[0] = mean;
        sh[1] = rsqrtf(var + 1e-6f);
    }
    __syncthreads();
    const float mean = sh[0], rstd = sh[1];
    const float a = rstd * gamma[ch];
    const float b = beta[ch] - mean * a;

    const float4* xp = (const float4*)(x + (size_t)bc * HW);
    __nv_bfloat162* o2 = (__nv_bfloat162*)(hn + (size_t)bc * HW);
#pragma unroll
    for (int k = 0; k < 4; k++) {
        int i = k * 256 + threadIdx.x;
        float4 v = xp[i];
        o2[2 * i]     = __floats2bfloat162_rn(v.x * a + b, v.y * a + b);
        o2[2 * i + 1] = __floats2bfloat162_rn(v.z * a + b, v.w * a + b);
    }
}

// ============================================================
// BF16 tensor-core GEMM, 256x128 block tile, warp tile 64x64, 3-stage pipe.
// C = alpha*op(A)*op(B) (+bias)(+resid fp32)
// ============================================================
template<bool AROW, bool BROW, typename OUT>
__global__ void __launch_bounds__(256) gemm_big(
    const __nv_bfloat16* __restrict__ A, const __nv_bfloat16* __restrict__ B,
    const float* __restrict__ bias, const float* __restrict__ Rsd,
    OUT* __restrict__ C,
    int K, int N, int lda, int ldb,
    size_t aStride, size_t bStride, size_t cStride, size_t rStride,
    float alpha)
{
    extern __shared__ char smem_c[];
    __nv_bfloat16* smemh = (__nv_bfloat16*)smem_c;
    using L = BigLay<AROW, BROW>;
    const int bz = blockIdx.z;
    A += aStride * bz; B += bStride * bz; C += cStride * bz;
    const float* R = Rsd ? (Rsd + rStride * bz) : nullptr;
    const int m0 = blockIdx.y * 256, n0 = blockIdx.x * 128;

    const int t = threadIdx.x;
    const int wid = t >> 5;
    const int wm = wid & 3;          // 4 warps x 64 rows
    const int wn = wid >> 2;         // 2 warps x 64 cols

    using ALay = typename std::conditional<AROW, wmma::row_major, wmma::col_major>::type;
    using BLay = typename std::conditional<BROW, wmma::row_major, wmma::col_major>::type;
    wmma::fragment<wmma::matrix_a, 16, 16, 16, __nv_bfloat16, ALay> af[4];
    wmma::fragment<wmma::matrix_b, 16, 16, 16, __nv_bfloat16, BLay> bf[4];
    wmma::fragment<wmma::accumulator, 16, 16, 16, float> acc[4][4];
#pragma unroll
    for (int i = 0; i < 4; i++)
#pragma unroll
        for (int j = 0; j < 4; j++)
            wmma::fill_fragment(acc[i][j], 0.f);

    auto load_stage = [&](int st, int k0) {
        __nv_bfloat16* As = smemh + st * L::STG;
        __nv_bfloat16* Bs = As + L::ASTG;
#pragma unroll
        for (int c = t; c < 1024; c += 256) {
            if (AROW) {                    // 256 rows x 32 k
                int m = c >> 2, kk = (c & 3) << 3;
                cp_async16(As + m * L::LDA + kk, A + (size_t)(m0 + m) * lda + k0 + kk);
            } else {                       // 32 k-rows x 256 m
                int k = c >> 5, mm = (c & 31) << 3;
                cp_async16(As + k * L::LDA + mm, A + (size_t)(k0 + k) * lda + m0 + mm);
            }
        }
#pragma unroll
        for (int c = t; c < 512; c += 256) {
            if (BROW) {                    // 32 k-rows x 128 n
                int k = c >> 4, nn = (c & 15) << 3;
                cp_async16(Bs + k * L::LDB + nn, B + (size_t)(k0 + k) * ldb + n0 + nn);
            } else {                       // 128 n-rows x 32 k
                int n = c >> 2, kk = (c & 3) << 3;
                cp_async16(Bs + n * L::LDB + kk, B + (size_t)(n0 + n) * ldb + k0 + kk);
            }
        }
    };

    const int KT = K >> 5;
    // 3-stage prologue: stages 0, 1 in flight
    load_stage(0, 0);
    cp_commit();
    if (KT > 1) load_stage(1, 32);
    cp_commit();

    int sidx = 0;                    // kt % 3
    for (int kt = 0; kt < KT; kt++) {
        int pf = kt + 2;
        if (pf < KT) {
            int pb = pf - 3 * (pf / 3);
            load_stage(pb, pf << 5);
        }
        cp_commit();                 // uniform group accounting
        cp_wait<2>();                // stage kt resident
        __syncthreads();

        const __nv_bfloat16* As = smemh + sidx * L::STG;
        const __nv_bfloat16* Bs = As + L::ASTG;
#pragma unroll
        for (int ks = 0; ks < 32; ks += 16) {
#pragma unroll
            for (int i = 0; i < 4; i++) {
                const __nv_bfloat16* ap = AROW
                    ? As + (wm * 64 + i * 16) * L::LDA + ks
                    : As + ks * L::LDA + (wm * 64 + i * 16);
                wmma::load_matrix_sync(af[i], ap, L::LDA);
            }
#pragma unroll
            for (int j = 0; j < 4; j++) {
                const __nv_bfloat16* bp = BROW
                    ? Bs + ks * L::LDB + (wn * 64 + j * 16)
                    : Bs + (wn * 64 + j * 16) * L::LDB + ks;
                wmma::load_matrix_sync(bf[j], bp, L::LDB);
            }
#pragma unroll
            for (int i = 0; i < 4; i++)
#pragma unroll
                for (int j = 0; j < 4; j++)
                    wmma::mma_sync(acc[i][j], af[i], bf[j], acc[i][j]);
        }
        __syncthreads();
        if (++sidx == 3) sidx = 0;
    }

    // ---- epilogue: two 128-row halves through 128x132 fp32 staging ----
    float* Csh = (float*)smem_c;
#pragma unroll
    for (int h = 0; h < 2; h++) {
        if ((wm >> 1) == h) {
#pragma unroll
            for (int i = 0; i < 4; i++)
#pragma unroll
                for (int j = 0; j < 4; j++)
                    wmma::store_matrix_sync(
                        Csh + ((wm & 1) * 64 + i * 16) * 132 + wn * 64 + j * 16,
                        acc[i][j], 132, wmma::mem_row_major);
        }
        __syncthreads();

        const int c4 = (t & 31) << 2;
        for (int r = t >> 5; r < 128; r += 8) {
            float4 v = *(const float4*)(Csh + r * 132 + c4);
            const int m = m0 + h * 128 + r;
            float bsv = bias ? bias[m] : 0.f;
            v.x = v.x * alpha + bsv;
            v.y = v.y * alpha + bsv;
            v.z = v.z * alpha + bsv;
            v.w = v.w * alpha + bsv;
            if (R) {
                float4 rv = *(const float4*)(R + (size_t)m * N + n0 + c4);
                v.x += rv.x; v.y += rv.y; v.z += rv.z; v.w += rv.w;
            }
            OUT* cp = C + (size_t)m * N + n0 + c4;
            if (std::is_same<OUT, float>::value) {
                *(float4*)(void*)cp = v;
            } else {
                ushort4 u;
                u.x = __bfloat16_as_ushort(__float2bfloat16(v.x));
                u.y = __bfloat16_as_ushort(__float2bfloat16(v.y));
                u.z = __bfloat16_as_ushort(__float2bfloat16(v.z));
                u.w = __bfloat16_as_ushort(__float2bfloat16(v.w));
                *(ushort4*)(void*)cp = u;
            }
        }
        __syncthreads();
    }
}

// ============================================================
// Softmax: single global read. Row (4096) cached in 16 regs/thread.
// ============================================================
__global__ void __launch_bounds__(256) softmax_kernel(
    const __nv_bfloat16* __restrict__ S, __nv_bfloat16* __restrict__ Aout)
{
    const __nv_bfloat162* row2 = (const __nv_bfloat162*)(S + (size_t)blockIdx.x * HW);
    __nv_bfloat162* arow2 = (__nv_bfloat162*)(Aout + (size_t)blockIdx.x * HW);
    const int t = threadIdx.x;
    __shared__ float sh[8];

    // single read: 8 bf16x2 per thread -> 16 fp32 regs
    float vals[16];
    float m = -1e30f;
#pragma unroll
    for (int k = 0; k < 8; k++) {
        float2 f = __bfloat1622float2(row2[t + k * 256]);
        vals[2 * k] = f.x; vals[2 * k + 1] = f.y;
        m = fmaxf(m, fmaxf(f.x, f.y));
    }
    for (int o = 16; o; o >>= 1) m = fmaxf(m, __shfl_xor_sync(0xffffffffu, m, o));
    if ((t & 31) == 0) sh[t >> 5] = m;
    __syncthreads();
    m = sh[0];
#pragma unroll
    for (int i = 1; i < 8; i++) m = fmaxf(m, sh[i]);

    float s = 0.f;
#pragma unroll
    for (int k = 0; k < 16; k++) {
        float e = __expf(vals[k] - m);
        vals[k] = e;
        s += e;
    }
    for (int o = 16; o; o >>= 1) s += __shfl_xor_sync(0xffffffffu, s, o);
    __syncthreads();
    if ((t & 31) == 0) sh[t >> 5] = s;
    __syncthreads();
    s = 0.f;
#pragma unroll
    for (int i = 0; i < 8; i++) s += sh[i];
    float inv = 1.f / s;
#pragma unroll
    for (int k = 0; k < 8; k++)
        arow2[t + k * 256] = __floats2bfloat162_rn(vals[2 * k] * inv, vals[2 * k + 1] * inv);
}

// ============================================================
// Launch
// ============================================================
extern "C" void kernel_launch(void* const* d_in, const int* in_sizes, int n_in,
                              void* d_out, int out_size)
{
    const float* x      = (const float*)d_in[0];
    const float* gamma  = (const float*)d_in[1];
    const float* beta   = (const float*)d_in[2];
    const float* qkv_w  = (const float*)d_in[3];
    const float* qkv_b  = (const float*)d_in[4];
    const float* proj_w = (const float*)d_in[5];
    const float* proj_b = (const float*)d_in[6];
    float* out = (float*)d_out;

    __nv_bfloat16 *hn, *qkv, *scores, *attn, *ao, *qw, *pw;
    float* stat;
    cudaGetSymbolAddress((void**)&hn, g_hn);
    cudaGetSymbolAddress((void**)&qkv, g_qkv);
    cudaGetSymbolAddress((void**)&scores, g_scores);
    cudaGetSymbolAddress((void**)&attn, g_attn);
    cudaGetSymbolAddress((void**)&ao, g_ao);
    cudaGetSymbolAddress((void**)&qw, g_qw_h);
    cudaGetSymbolAddress((void**)&pw, g_pw_h);
    cudaGetSymbolAddress((void**)&stat, g_gnstat);

    cudaFuncSetAttribute(gemm_big<true,  true,  __nv_bfloat16>, cudaFuncAttributeMaxDynamicSharedMemorySize, BigLay<true,  true >::BYTES);
    cudaFuncSetAttribute(gemm_big<false, true,  __nv_bfloat16>, cudaFuncAttributeMaxDynamicSharedMemorySize, BigLay<false, true >::BYTES);
    cudaFuncSetAttribute(gemm_big<true,  false, __nv_bfloat16>, cudaFuncAttributeMaxDynamicSharedMemorySize, BigLay<true,  false>::BYTES);
    cudaFuncSetAttribute(gemm_big<true,  true,  float>,         cudaFuncAttributeMaxDynamicSharedMemorySize, BigLay<true,  true >::BYTES);

    // 0-1) weight conversions
    cvt_kernel<<<264, 256>>>(qkv_w, qw, NQKV * CC);
    cvt_kernel<<<264, 256>>>(proj_w, pw, CC * CC);

    // 2) GroupNorm stats
    gn_stats<<<BB * NG * 8, 256>>>(x, stat);

    // 3) GroupNorm apply -> bf16 hn
    gn_apply<<<BB * CC, 256>>>(x, stat, gamma, beta, hn);

    // 4) QKV = W_qkv @ hn + b
    {
        dim3 grid(HW / 128, NQKV / 256, BB);
        gemm_big<true, true, __nv_bfloat16><<<grid, 256, BigLay<true, true>::BYTES>>>(
            qw, hn, qkv_b, nullptr, qkv,
            CC, HW, CC, HW,
            0, (size_t)CC * HW, (size_t)NQKV * HW, 0, 1.f);
    }

    // 5) scores = scale * Q^T K
    {
        dim3 grid(HW / 128, HW / 256, BB);
        gemm_big<false, true, __nv_bfloat16><<<grid, 256, BigLay<false, true>::BYTES>>>(
            qkv, qkv + (size_t)CC * HW, nullptr, nullptr, scores,
            CC, HW, HW, HW,
            (size_t)NQKV * HW, (size_t)NQKV * HW, (size_t)HW * HW, 0,
            0.04419417382415922f);
    }

    // 6) softmax rows -> bf16
    softmax_kernel<<<BB * HW, 256>>>(scores, attn);

    // 7) attnout = V @ attn^T
    {
        dim3 grid(HW / 128, CC / 256, BB);
        gemm_big<true, false, __nv_bfloat16><<<grid, 256, BigLay<true, false>::BYTES>>>(
            qkv + (size_t)2 * CC * HW, attn, nullptr, nullptr, ao,
            HW, HW, HW, HW,
            (size_t)NQKV * HW, (size_t)HW * HW, (size_t)CC * HW, 0, 1.f);
    }

    // 8) out = x + proj_w @ attnout + proj_b
    {
        dim3 grid(HW / 128, CC / 256, BB);
        gemm_big<true, true, float><<<grid, 256, BigLay<true, true>::BYTES>>>(
            pw, ao, proj_b, x, out,
            CC, HW, CC, HW,
            0, (size_t)CC * HW, (size_t)CC * HW, (size_t)CC * HW, 1.f);
    }
}